// round 3
// baseline (speedup 1.0000x reference)
#include <cuda_runtime.h>
#include <math.h>

#define BATCH 64
#define SEQT  2048
#define ISZ   256
#define HSZ   1024
#define NMOD  8

// 512 MB scratch for the precomputed input projection, laid out [t][b][h]
static __device__ float g_xproj[(size_t)SEQT * BATCH * HSZ];

// ---------------------------------------------------------------------------
// Kernel 1: xproj[t][b][:] = x[b][t][:] @ W_ih^T + (b_ih + b_hh)
// Classic 128x128x32 fp32 SGEMM. M = B*T = 131072 rows, N = H = 1024, K = 256.
// Both A (x) and B (W_ih) are K-major row-major -> NT-style dot of rows.
// ---------------------------------------------------------------------------
__global__ __launch_bounds__(256, 2)
void xproj_gemm(const float* __restrict__ X, const float* __restrict__ Wih,
                const float* __restrict__ bih, const float* __restrict__ bhh)
{
    __shared__ float As[32][132];   // padded: 132*4 = 528 bytes (16B aligned rows)
    __shared__ float Bs[32][132];

    const int bm = blockIdx.x;      // 0..1023  (row tiles of 128)
    const int bn = blockIdx.y;      // 0..7     (col tiles of 128)
    const int tid = threadIdx.x;
    const int tx = tid & 15;
    const int ty = tid >> 4;

    float acc[8][8];
#pragma unroll
    for (int i = 0; i < 8; i++)
#pragma unroll
        for (int j = 0; j < 8; j++) acc[i][j] = 0.f;

    const float* Ab = X   + (size_t)bm * 128 * ISZ;
    const float* Bb = Wih + (size_t)bn * 128 * ISZ;
    const int lr = tid >> 3;          // 0..31
    const int lc = (tid & 7) << 2;    // 0,4,...,28

    for (int k0 = 0; k0 < ISZ; k0 += 32) {
#pragma unroll
        for (int q = 0; q < 4; q++) {
            int row = lr + q * 32;
            float4 va = *(const float4*)(Ab + (size_t)row * ISZ + k0 + lc);
            As[lc + 0][row] = va.x; As[lc + 1][row] = va.y;
            As[lc + 2][row] = va.z; As[lc + 3][row] = va.w;
            float4 vb = *(const float4*)(Bb + (size_t)row * ISZ + k0 + lc);
            Bs[lc + 0][row] = vb.x; Bs[lc + 1][row] = vb.y;
            Bs[lc + 2][row] = vb.z; Bs[lc + 3][row] = vb.w;
        }
        __syncthreads();
#pragma unroll
        for (int kk = 0; kk < 32; kk++) {
            float a[8], bb[8];
            float4 a0 = *(const float4*)&As[kk][ty * 8];
            float4 a1 = *(const float4*)&As[kk][ty * 8 + 4];
            float4 b0 = *(const float4*)&Bs[kk][tx * 8];
            float4 b1 = *(const float4*)&Bs[kk][tx * 8 + 4];
            a[0] = a0.x; a[1] = a0.y; a[2] = a0.z; a[3] = a0.w;
            a[4] = a1.x; a[5] = a1.y; a[6] = a1.z; a[7] = a1.w;
            bb[0] = b0.x; bb[1] = b0.y; bb[2] = b0.z; bb[3] = b0.w;
            bb[4] = b1.x; bb[5] = b1.y; bb[6] = b1.z; bb[7] = b1.w;
#pragma unroll
            for (int i = 0; i < 8; i++)
#pragma unroll
                for (int j = 0; j < 8; j++)
                    acc[i][j] = fmaf(a[i], bb[j], acc[i][j]);
        }
        __syncthreads();
    }

    // Epilogue: add (b_ih + b_hh), remap row bt=(b*T+t) -> xproj[(t*B+b)]
    const int colbase = bn * 128 + tx * 8;
    float bsum[8];
#pragma unroll
    for (int j = 0; j < 8; j++)
        bsum[j] = __ldg(bih + colbase + j) + __ldg(bhh + colbase + j);

#pragma unroll
    for (int i = 0; i < 8; i++) {
        int row = bm * 128 + ty * 8 + i;     // bt index
        int tt  = row & (SEQT - 1);          // t
        int bb2 = row >> 11;                 // b  (T = 2^11)
        float* cr = g_xproj + ((size_t)tt * BATCH + bb2) * HSZ + colbase;
        float4 v0, v1;
        v0.x = acc[i][0] + bsum[0]; v0.y = acc[i][1] + bsum[1];
        v0.z = acc[i][2] + bsum[2]; v0.w = acc[i][3] + bsum[3];
        v1.x = acc[i][4] + bsum[4]; v1.y = acc[i][5] + bsum[5];
        v1.z = acc[i][6] + bsum[6]; v1.w = acc[i][7] + bsum[7];
        *(float4*)cr       = v0;
        *(float4*)(cr + 4) = v1;
    }
}

// ---------------------------------------------------------------------------
// Kernel 2: sequential clockwork recurrence. One CTA per batch element,
// 1024 threads, persistent loop over T steps. Shared-memory state:
//   h[1024]        current hidden state
//   s[36][128]     cached recurrent partials: s[p(i,j)] = W_blk(i,j) @ h_j
//   c[8][256]      cached output contributions: c[m] = fc_w_blk(m) @ h_m
// Per step t (nact = # active blocks = min(ctz(t)+1, 8); t=0 -> 8):
//   P1: for active rows r: h[r] = tanh(xproj[t][r] + sum_{j>=i} s[i][j][r])
//   P3: for active j, i<=j: recompute s[i][j] from new h_j      (16K MAC each)
//   P4: for active m: recompute c[m] from new h_m               (32K MAC each)
//   P5: y[t] = sum_m c[m] + fc_b
// ---------------------------------------------------------------------------
__global__ __launch_bounds__(1024, 1)
void cwrnn(const float* __restrict__ Whh, const float* __restrict__ fcw,
           const float* __restrict__ fcb, float* __restrict__ out)
{
    __shared__ __align__(16) float h[HSZ];
    __shared__ float s[36 * 128];
    __shared__ float c[8 * 256];
    __shared__ unsigned char pi[36], pj[36];

    const int b   = blockIdx.x;
    const int tid = threadIdx.x;
    const float* xp = g_xproj + (size_t)b * HSZ;   // + t*BATCH*HSZ per step
    float* ob = out + (size_t)b * SEQT * ISZ;

    // init state (h0 = 0 -> all cached partials 0)
    h[tid] = 0.f;
    for (int k = tid; k < 36 * 128; k += 1024) s[k] = 0.f;
    if (tid == 0) {
        int p = 0;
        for (int j = 0; j < 8; j++)
            for (int i = 0; i <= j; i++) { pi[p] = (unsigned char)i; pj[p] = (unsigned char)j; p++; }
    }
    __syncthreads();

    float xreg = __ldg(xp + tid);   // prefetch xproj[0][b][tid]

    for (int t = 0; t < SEQT; t++) {
        const int nact = (t == 0) ? 8 : min(__ffs(t), 8);
        const int rows = nact << 7;

        // prefetch next step's xproj element for this thread (hides L2/DRAM)
        float xnext = 0.f;
        if (t + 1 < SEQT)
            xnext = __ldg(xp + (size_t)(t + 1) * BATCH * HSZ + tid);

        // ---- P1: update h for active rows from cached partials ----
        if (tid < rows) {
            const int i  = tid >> 7;
            const int rr = tid & 127;
            float v = xreg;
            for (int j = i; j < 8; j++)
                v += s[(((j * (j + 1)) >> 1) + i) * 128 + rr];
            h[tid] = tanhf(v);
        }
        __syncthreads();   // S1: h ready

        // ---- P3: recompute s[i][j] for all pairs with active j ----
        {
            const int P    = (nact * (nact + 1)) >> 1;       // 1,3,6,...,36
            const int outs = P << 7;
            const int L    = (outs <= 128) ? 8 : ((outs <= 512) ? 2 : 1);
            const int lane = tid & (L - 1);
            const int step = 1024 / L;
            const int n4   = 32 / L;                         // float4s per lane
            for (int o = tid / L; o < outs; o += step) {
                const int p  = o >> 7;
                const int rr = o & 127;
                const int i  = pi[p], j = pj[p];
                const float4* wr = (const float4*)(Whh + (size_t)((i << 7) + rr) * HSZ + (j << 7));
                const float4* hv = (const float4*)(h + (j << 7));
                const int base = lane * n4;
                float v = 0.f;
#pragma unroll 8
                for (int q = 0; q < n4; q++) {
                    float4 w4 = __ldg(wr + base + q);
                    float4 h4 = hv[base + q];
                    v = fmaf(w4.x, h4.x, fmaf(w4.y, h4.y, fmaf(w4.z, h4.z, fmaf(w4.w, h4.w, v))));
                }
                for (int off = L >> 1; off; off >>= 1)
                    v += __shfl_xor_sync(0xffffffffu, v, off);
                if (lane == 0) s[(p << 7) + rr] = v;
            }
        }

        // ---- P4: recompute c[m] for active m (m < nact) ----
        {
            const int outs = nact << 8;
            const int L    = (outs <= 256) ? 4 : ((outs <= 512) ? 2 : 1);
            const int lane = tid & (L - 1);
            const int step = 1024 / L;
            const int n4   = 32 / L;
            for (int o = tid / L; o < outs; o += step) {
                const int m  = o >> 8;
                const int oo = o & 255;
                const float4* wr = (const float4*)(fcw + (size_t)oo * HSZ + (m << 7));
                const float4* hv = (const float4*)(h + (m << 7));
                const int base = lane * n4;
                float v = 0.f;
#pragma unroll 8
                for (int q = 0; q < n4; q++) {
                    float4 w4 = __ldg(wr + base + q);
                    float4 h4 = hv[base + q];
                    v = fmaf(w4.x, h4.x, fmaf(w4.y, h4.y, fmaf(w4.z, h4.z, fmaf(w4.w, h4.w, v))));
                }
                for (int off = L >> 1; off; off >>= 1)
                    v += __shfl_xor_sync(0xffffffffu, v, off);
                if (lane == 0) c[(m << 8) + oo] = v;
            }
        }
        __syncthreads();   // S2: s, c ready

        // ---- P5: y[t] = sum_m c[m] + fc_b ----
        if (tid < ISZ) {
            float v = __ldg(fcb + tid);
#pragma unroll
            for (int m = 0; m < 8; m++) v += c[(m << 8) + tid];
            ob[(size_t)t * ISZ + tid] = v;
        }

        xreg = xnext;
    }
}

// ---------------------------------------------------------------------------
// Launch: GEMM (parallel) then recurrence (sequential, 64 independent CTAs).
// Same stream -> ordered. Graph-capturable: 2 kernel launches, no allocs.
// Inputs (metadata order): x, weight_ih, weight_hh, bias_ih, bias_hh,
//                          fc_w, fc_b, n_modules(=8, ignored)
// ---------------------------------------------------------------------------
extern "C" void kernel_launch(void* const* d_in, const int* in_sizes, int n_in,
                              void* d_out, int out_size)
{
    const float* x   = (const float*)d_in[0];
    const float* wih = (const float*)d_in[1];
    const float* whh = (const float*)d_in[2];
    const float* bih = (const float*)d_in[3];
    const float* bhh = (const float*)d_in[4];
    const float* fcw = (const float*)d_in[5];
    const float* fcb = (const float*)d_in[6];
    float* out = (float*)d_out;

    dim3 ggrid((BATCH * SEQT) / 128, HSZ / 128);
    xproj_gemm<<<ggrid, 256>>>(x, wih, bih, bhh);
    cwrnn<<<BATCH, 1024>>>(whh, fcw, fcb, out);
}

// round 4
// speedup vs baseline: 4.6134x; 4.6134x over previous
#include <cuda_runtime.h>
#include <math.h>

#define BATCH 64
#define SEQT  2048
#define ISZ   256
#define HSZ   1024
#define NMOD  8

// 512 MB scratch for the precomputed input projection, laid out [t][b][h]
static __device__ float g_xproj[(size_t)SEQT * BATCH * HSZ];

// ---------------------------------------------------------------------------
// Kernel 1: xproj[t][b][:] = x[b][t][:] @ W_ih^T + (b_ih + b_hh)
// 128x128x32 fp32 SGEMM. M = B*T = 131072, N = H = 1024, K = 256.
// ---------------------------------------------------------------------------
__global__ __launch_bounds__(256, 2)
void xproj_gemm(const float* __restrict__ X, const float* __restrict__ Wih,
                const float* __restrict__ bih, const float* __restrict__ bhh)
{
    __shared__ float As[32][132];
    __shared__ float Bs[32][132];

    const int bm = blockIdx.x;
    const int bn = blockIdx.y;
    const int tid = threadIdx.x;
    const int tx = tid & 15;
    const int ty = tid >> 4;

    float acc[8][8];
#pragma unroll
    for (int i = 0; i < 8; i++)
#pragma unroll
        for (int j = 0; j < 8; j++) acc[i][j] = 0.f;

    const float* Ab = X   + (size_t)bm * 128 * ISZ;
    const float* Bb = Wih + (size_t)bn * 128 * ISZ;
    const int lr = tid >> 3;
    const int lc = (tid & 7) << 2;

    for (int k0 = 0; k0 < ISZ; k0 += 32) {
#pragma unroll
        for (int q = 0; q < 4; q++) {
            int row = lr + q * 32;
            float4 va = *(const float4*)(Ab + (size_t)row * ISZ + k0 + lc);
            As[lc + 0][row] = va.x; As[lc + 1][row] = va.y;
            As[lc + 2][row] = va.z; As[lc + 3][row] = va.w;
            float4 vb = *(const float4*)(Bb + (size_t)row * ISZ + k0 + lc);
            Bs[lc + 0][row] = vb.x; Bs[lc + 1][row] = vb.y;
            Bs[lc + 2][row] = vb.z; Bs[lc + 3][row] = vb.w;
        }
        __syncthreads();
#pragma unroll
        for (int kk = 0; kk < 32; kk++) {
            float a[8], bb[8];
            float4 a0 = *(const float4*)&As[kk][ty * 8];
            float4 a1 = *(const float4*)&As[kk][ty * 8 + 4];
            float4 b0 = *(const float4*)&Bs[kk][tx * 8];
            float4 b1 = *(const float4*)&Bs[kk][tx * 8 + 4];
            a[0] = a0.x; a[1] = a0.y; a[2] = a0.z; a[3] = a0.w;
            a[4] = a1.x; a[5] = a1.y; a[6] = a1.z; a[7] = a1.w;
            bb[0] = b0.x; bb[1] = b0.y; bb[2] = b0.z; bb[3] = b0.w;
            bb[4] = b1.x; bb[5] = b1.y; bb[6] = b1.z; bb[7] = b1.w;
#pragma unroll
            for (int i = 0; i < 8; i++)
#pragma unroll
                for (int j = 0; j < 8; j++)
                    acc[i][j] = fmaf(a[i], bb[j], acc[i][j]);
        }
        __syncthreads();
    }

    const int colbase = bn * 128 + tx * 8;
    float bsum[8];
#pragma unroll
    for (int j = 0; j < 8; j++)
        bsum[j] = __ldg(bih + colbase + j) + __ldg(bhh + colbase + j);

#pragma unroll
    for (int i = 0; i < 8; i++) {
        int row = bm * 128 + ty * 8 + i;
        int tt  = row & (SEQT - 1);
        int bb2 = row >> 11;
        float* cr = g_xproj + ((size_t)tt * BATCH + bb2) * HSZ + colbase;
        float4 v0, v1;
        v0.x = acc[i][0] + bsum[0]; v0.y = acc[i][1] + bsum[1];
        v0.z = acc[i][2] + bsum[2]; v0.w = acc[i][3] + bsum[3];
        v1.x = acc[i][4] + bsum[4]; v1.y = acc[i][5] + bsum[5];
        v1.z = acc[i][6] + bsum[6]; v1.w = acc[i][7] + bsum[7];
        *(float4*)cr       = v0;
        *(float4*)(cr + 4) = v1;
    }
}

// ---------------------------------------------------------------------------
// Kernel 2: sequential clockwork recurrence. One CTA per batch element.
// Dynamic SMEM layout (227,328 B):
//   h[1024]          hidden state
//   s[36*128]        cached recurrent partials  s[p(i,j)] = W_blk(i,j) @ h_j
//   c[8*256]         cached output contributions c[m] = fc_blk(m) @ h_m
//   W00[128*128]     pinned W_hh block (0,0)  -- needed EVERY step
//   FC0[256*128]     pinned fc_w block m=0    -- needed EVERY step
// Per step: Phase B (global weights for modules >=1, only on even steps,
// coalesced 128B segments, issued first) + Phase A (pinned SMEM matvecs,
// warp-per-output, conflict-free). Only 2 barriers per step.
// ---------------------------------------------------------------------------
#define SMEM_FLOATS (1024 + 36*128 + 8*256 + 128*128 + 256*128)
#define SMEM_BYTES  (SMEM_FLOATS * 4)

__global__ __launch_bounds__(1024, 1)
void cwrnn(const float* __restrict__ Whh, const float* __restrict__ fcw,
           const float* __restrict__ fcb, float* __restrict__ out)
{
    extern __shared__ float smem[];
    float* h   = smem;                 // 1024
    float* s   = h + 1024;             // 4608
    float* c   = s + 36 * 128;         // 2048
    float* W00 = c + 8 * 256;          // 16384
    float* FC0 = W00 + 128 * 128;      // 32768

    __shared__ unsigned char spi[36], spj[36];

    const int b    = blockIdx.x;
    const int tid  = threadIdx.x;
    const int wid  = tid >> 5;
    const int lane = tid & 31;
    const float* xp = g_xproj + (size_t)b * HSZ;
    float* ob = out + (size_t)b * SEQT * ISZ;

    // ---- init: zero state, preload pinned weight blocks ----
    h[tid] = 0.f;
    for (int k = tid; k < 36 * 128; k += 1024) s[k] = 0.f;
    // W00 = Whh[0:128, 0:128]  (4096 float4)
    for (int idx = tid; idx < 128 * 32; idx += 1024) {
        int r = idx >> 5, q = idx & 31;
        ((float4*)W00)[idx] = __ldg((const float4*)(Whh + (size_t)r * HSZ) + q);
    }
    // FC0 = fcw[0:256, 0:128]  (8192 float4)
    for (int idx = tid; idx < 256 * 32; idx += 1024) {
        int r = idx >> 5, q = idx & 31;
        ((float4*)FC0)[idx] = __ldg((const float4*)(fcw + (size_t)r * HSZ) + q);
    }
    if (tid == 0) {
        int p = 0;
        for (int j = 0; j < 8; j++)
            for (int i = 0; i <= j; i++) { spi[p] = (unsigned char)i; spj[p] = (unsigned char)j; p++; }
    }
    __syncthreads();

    float xreg = __ldg(xp + tid);   // xproj[0][b][tid]

    for (int t = 0; t < SEQT; t++) {
        const int nact = (t == 0) ? 8 : min(__ffs(t), 8);
        const int rows = nact << 7;

        // prefetch next step's xproj element
        float xnext = 0.f;
        if (t + 1 < SEQT)
            xnext = __ldg(xp + (size_t)(t + 1) * BATCH * HSZ + tid);

        // ---- P1: h update for active rows from cached partials ----
        if (tid < rows) {
            const int i  = tid >> 7;
            const int rr = tid & 127;
            float v = xreg;
#pragma unroll
            for (int j = 0; j < 8; j++) {
                float sv = s[((((j * (j + 1)) >> 1) + i) << 7) + rr];
                if (j >= i) v += sv;
            }
            h[tid] = tanhf(v);
        }
        __syncthreads();   // S1: h ready; prior-step readers of s/c done

        // ---- Phase B (even steps): global weights for modules >= 1 ----
        if (nact > 1) {
            const int P      = (nact * (nact + 1)) >> 1;
            const int outs_s = (P - 1) << 7;
            const int outs   = outs_s + ((nact - 1) << 8);
            const int lane8  = tid & 7;
            for (int o = tid >> 3; o < outs; o += 128) {
                const float4* wrow;
                const float4* hb;
                float* dst;
                if (o < outs_s) {
                    int p  = 1 + (o >> 7);
                    int rr = o & 127;
                    int i = spi[p], j = spj[p];
                    wrow = (const float4*)(Whh + (((size_t)((i << 7) + rr)) << 10) + (j << 7));
                    hb   = (const float4*)(h + (j << 7));
                    dst  = s + (p << 7) + rr;
                } else {
                    int o2 = o - outs_s;
                    int m  = 1 + (o2 >> 8);
                    int oo = o2 & 255;
                    wrow = (const float4*)(fcw + (((size_t)oo) << 10) + (m << 7));
                    hb   = (const float4*)(h + (m << 7));
                    dst  = c + (m << 8) + oo;
                }
                float v = 0.f;
#pragma unroll
                for (int q = 0; q < 4; q++) {
                    float4 w4 = __ldg(wrow + q * 8 + lane8);
                    float4 h4 = hb[q * 8 + lane8];
                    v = fmaf(w4.x, h4.x, fmaf(w4.y, h4.y, fmaf(w4.z, h4.z, fmaf(w4.w, h4.w, v))));
                }
                v += __shfl_xor_sync(0xffffffffu, v, 4);
                v += __shfl_xor_sync(0xffffffffu, v, 2);
                v += __shfl_xor_sync(0xffffffffu, v, 1);
                if (lane8 == 0) *dst = v;
            }
        }

        // ---- Phase A (every step): pinned SMEM matvecs, warp-per-output ----
        {
            float4 h0 = ((const float4*)h)[lane];   // h[0:128]
#pragma unroll
            for (int k = 0; k < 12; k++) {
                int task = wid + (k << 5);          // 0..383
                const float4* wrow = (task < 128)
                    ? (const float4*)W00 + (task << 5)
                    : (const float4*)FC0 + ((task - 128) << 5);
                float4 w4 = wrow[lane];
                float v = fmaf(w4.x, h0.x, fmaf(w4.y, h0.y, fmaf(w4.z, h0.z, w4.w * h0.w)));
                v += __shfl_xor_sync(0xffffffffu, v, 16);
                v += __shfl_xor_sync(0xffffffffu, v, 8);
                v += __shfl_xor_sync(0xffffffffu, v, 4);
                v += __shfl_xor_sync(0xffffffffu, v, 2);
                v += __shfl_xor_sync(0xffffffffu, v, 1);
                if (lane == 0) {
                    if (task < 128) s[task] = v;
                    else            c[task - 128] = v;
                }
            }
        }
        __syncthreads();   // S2: s, c ready

        // ---- P5: y[t] = sum_m c[m] + fc_b ----
        if (tid < ISZ) {
            float v = __ldg(fcb + tid);
#pragma unroll
            for (int m = 0; m < 8; m++) v += c[(m << 8) + tid];
            ob[(size_t)t * ISZ + tid] = v;
        }

        xreg = xnext;
    }
}

// ---------------------------------------------------------------------------
extern "C" void kernel_launch(void* const* d_in, const int* in_sizes, int n_in,
                              void* d_out, int out_size)
{
    const float* x   = (const float*)d_in[0];
    const float* wih = (const float*)d_in[1];
    const float* whh = (const float*)d_in[2];
    const float* bih = (const float*)d_in[3];
    const float* bhh = (const float*)d_in[4];
    const float* fcw = (const float*)d_in[5];
    const float* fcb = (const float*)d_in[6];
    float* out = (float*)d_out;

    cudaFuncSetAttribute(cwrnn, cudaFuncAttributeMaxDynamicSharedMemorySize, SMEM_BYTES);

    dim3 ggrid((BATCH * SEQT) / 128, HSZ / 128);
    xproj_gemm<<<ggrid, 256>>>(x, wih, bih, bhh);
    cwrnn<<<BATCH, 1024, SMEM_BYTES>>>(whh, fcw, fcb, out);
}

// round 5
// speedup vs baseline: 6.7535x; 1.4639x over previous
#include <cuda_runtime.h>
#include <math.h>
#include <stdint.h>

#define BATCH 64
#define SEQT  2048
#define ISZ   256
#define HSZ   1024

// 512 MB scratch for the precomputed input projection, laid out [t][b][h]
static __device__ float g_xproj[(size_t)SEQT * BATCH * HSZ];

// ---------------------------------------------------------------------------
// Kernel 1: xproj[t][b][:] = x[b][t][:] @ W_ih^T + (b_ih + b_hh)
// 128x128x32 fp32 SGEMM. M = B*T = 131072, N = H = 1024, K = 256.
// ---------------------------------------------------------------------------
__global__ __launch_bounds__(256, 2)
void xproj_gemm(const float* __restrict__ X, const float* __restrict__ Wih,
                const float* __restrict__ bih, const float* __restrict__ bhh)
{
    __shared__ float As[32][132];
    __shared__ float Bs[32][132];

    const int bm = blockIdx.x;
    const int bn = blockIdx.y;
    const int tid = threadIdx.x;
    const int tx = tid & 15;
    const int ty = tid >> 4;

    float acc[8][8];
#pragma unroll
    for (int i = 0; i < 8; i++)
#pragma unroll
        for (int j = 0; j < 8; j++) acc[i][j] = 0.f;

    const float* Ab = X   + (size_t)bm * 128 * ISZ;
    const float* Bb = Wih + (size_t)bn * 128 * ISZ;
    const int lr = tid >> 3;
    const int lc = (tid & 7) << 2;

    for (int k0 = 0; k0 < ISZ; k0 += 32) {
#pragma unroll
        for (int q = 0; q < 4; q++) {
            int row = lr + q * 32;
            float4 va = *(const float4*)(Ab + (size_t)row * ISZ + k0 + lc);
            As[lc + 0][row] = va.x; As[lc + 1][row] = va.y;
            As[lc + 2][row] = va.z; As[lc + 3][row] = va.w;
            float4 vb = *(const float4*)(Bb + (size_t)row * ISZ + k0 + lc);
            Bs[lc + 0][row] = vb.x; Bs[lc + 1][row] = vb.y;
            Bs[lc + 2][row] = vb.z; Bs[lc + 3][row] = vb.w;
        }
        __syncthreads();
#pragma unroll
        for (int kk = 0; kk < 32; kk++) {
            float a[8], bb[8];
            float4 a0 = *(const float4*)&As[kk][ty * 8];
            float4 a1 = *(const float4*)&As[kk][ty * 8 + 4];
            float4 b0 = *(const float4*)&Bs[kk][tx * 8];
            float4 b1 = *(const float4*)&Bs[kk][tx * 8 + 4];
            a[0] = a0.x; a[1] = a0.y; a[2] = a0.z; a[3] = a0.w;
            a[4] = a1.x; a[5] = a1.y; a[6] = a1.z; a[7] = a1.w;
            bb[0] = b0.x; bb[1] = b0.y; bb[2] = b0.z; bb[3] = b0.w;
            bb[4] = b1.x; bb[5] = b1.y; bb[6] = b1.z; bb[7] = b1.w;
#pragma unroll
            for (int i = 0; i < 8; i++)
#pragma unroll
                for (int j = 0; j < 8; j++)
                    acc[i][j] = fmaf(a[i], bb[j], acc[i][j]);
        }
        __syncthreads();
    }

    const int colbase = bn * 128 + tx * 8;
    float bsum[8];
#pragma unroll
    for (int j = 0; j < 8; j++)
        bsum[j] = __ldg(bih + colbase + j) + __ldg(bhh + colbase + j);

#pragma unroll
    for (int i = 0; i < 8; i++) {
        int row = bm * 128 + ty * 8 + i;
        int tt  = row & (SEQT - 1);
        int bb2 = row >> 11;
        float* cr = g_xproj + ((size_t)tt * BATCH + bb2) * HSZ + colbase;
        float4 v0, v1;
        v0.x = acc[i][0] + bsum[0]; v0.y = acc[i][1] + bsum[1];
        v0.z = acc[i][2] + bsum[2]; v0.w = acc[i][3] + bsum[3];
        v1.x = acc[i][4] + bsum[4]; v1.y = acc[i][5] + bsum[5];
        v1.z = acc[i][6] + bsum[6]; v1.w = acc[i][7] + bsum[7];
        *(float4*)cr       = v0;
        *(float4*)(cr + 4) = v1;
    }
}

// ---------------------------------------------------------------------------
// Cluster/mbarrier helpers
// ---------------------------------------------------------------------------
__device__ __forceinline__ uint32_t smem_u32(const void* p) {
    uint32_t a;
    asm("{ .reg .u64 t; cvta.to.shared.u64 t, %1; cvt.u32.u64 %0, t; }" : "=r"(a) : "l"(p));
    return a;
}
__device__ __forceinline__ void mbar_init(uint32_t a, uint32_t cnt) {
    asm volatile("mbarrier.init.shared.b64 [%0], %1;" :: "r"(a), "r"(cnt) : "memory");
}
__device__ __forceinline__ void mbar_wait_acq(uint32_t a, uint32_t parity) {
    asm volatile(
        "{\n\t.reg .pred P;\n\t"
        "W_%=:\n\t"
        "mbarrier.try_wait.parity.acquire.cluster.shared::cta.b64 P, [%0], %1, 0x989680;\n\t"
        "@!P bra W_%=;\n\t}"
        :: "r"(a), "r"(parity) : "memory");
}
__device__ __forceinline__ void mbar_arrive_remote(uint32_t local_a, uint32_t rank) {
    asm volatile(
        "{\n\t.reg .b32 ra;\n\t"
        "mapa.shared::cluster.u32 ra, %0, %1;\n\t"
        "mbarrier.arrive.release.cluster.shared::cluster.b64 _, [ra];\n\t}"
        :: "r"(local_a), "r"(rank) : "memory");
}
__device__ __forceinline__ void st_remote_f32(uint32_t local_a, uint32_t rank, float v) {
    asm volatile(
        "{\n\t.reg .b32 ra;\n\t"
        "mapa.shared::cluster.u32 ra, %0, %1;\n\t"
        "st.shared::cluster.f32 [ra], %2;\n\t}"
        :: "r"(local_a), "r"(rank), "f"(v) : "memory");
}
__device__ __forceinline__ void cluster_sync_() {
    asm volatile("barrier.cluster.arrive.aligned;" ::: "memory");
    asm volatile("barrier.cluster.wait.aligned;" ::: "memory");
}

// ---------------------------------------------------------------------------
// Kernel 2: clockwork recurrence, cluster-of-2 per batch element.
//   rank0 (recurrence): pins W00/W01/W11 (192KB), maintains h and s-partials,
//     pushes active h rows to rank1 via DSMEM each step.
//   rank1 (output): pins FC0 (128KB), updates c[m] for active m
//     (m=0 from smem, m>=1 from L2), computes y[t] and stores it.
// Double-buffered h slots; mbarrier h_ready[2] (rank1) / slot_free[2] (rank0).
// Dynamic smem = 219,136 B (rank0's layout is the max).
// ---------------------------------------------------------------------------
#define CW_SMEM_BYTES ((1024 + 36*128 + 3*128*128) * 4)

__global__ __launch_bounds__(1024, 1) __cluster_dims__(2, 1, 1)
void cwrnn(const float* __restrict__ Whh, const float* __restrict__ fcw,
           const float* __restrict__ fcb, float* __restrict__ out)
{
    extern __shared__ float dyn[];
    __shared__ __align__(8) unsigned long long bars[4];  // [0..1]=h_ready, [2..3]=slot_free
    __shared__ unsigned char spi[36], spj[36];

    const int tid  = threadIdx.x;
    const int wid  = tid >> 5;
    const int lane = tid & 31;
    const uint32_t rank = blockIdx.x & 1;
    const int b = blockIdx.x >> 1;
    const uint32_t dynb = smem_u32(dyn);
    const uint32_t barb = smem_u32(bars);

    if (tid == 0) {
        mbar_init(barb + 0, 1);
        mbar_init(barb + 8, 1);
        mbar_init(barb + 16, 1);
        mbar_init(barb + 24, 1);
        int p = 0;
        for (int j = 0; j < 8; j++)
            for (int i = 0; i <= j; i++) { spi[p] = (unsigned char)i; spj[p] = (unsigned char)j; p++; }
    }

    // role-specific smem preload
    if (rank == 0) {
        float* h   = dyn;
        float* s   = dyn + 1024;
        float* W00 = dyn + 1024 + 36 * 128;
        float* W01 = W00 + 128 * 128;
        float* W11 = W01 + 128 * 128;
        for (int idx = tid; idx < 128 * 32; idx += 1024) {
            int r = idx >> 5, q = idx & 31;
            ((float4*)W00)[idx] = __ldg((const float4*)(Whh + (size_t)r * HSZ) + q);
            ((float4*)W01)[idx] = __ldg((const float4*)(Whh + (size_t)r * HSZ) + 32 + q);
            ((float4*)W11)[idx] = __ldg((const float4*)(Whh + (size_t)(128 + r) * HSZ) + 32 + q);
        }
        h[tid] = 0.f;
        for (int k = tid; k < 36 * 128; k += 1024) s[k] = 0.f;
    } else {
        float* FC0 = dyn + 4096;   // hin[2][1024] | c[2048] | FC0[32768]
        for (int idx = tid; idx < 256 * 32; idx += 1024) {
            int r = idx >> 5, q = idx & 31;
            ((float4*)FC0)[idx] = __ldg((const float4*)(fcw + (size_t)r * HSZ) + q);
        }
    }
    __syncthreads();
    cluster_sync_();   // mbarriers + smem visible cluster-wide

    if (rank == 0) {
        // ================= recurrence CTA =================
        float* h   = dyn;
        float* s   = dyn + 1024;
        float* W00 = dyn + 1024 + 36 * 128;
        float* W01 = W00 + 128 * 128;
        float* W11 = W01 + 128 * 128;
        const float* xp = g_xproj + (size_t)b * HSZ;
        float xreg = __ldg(xp + tid);

        for (int t = 0; t < SEQT; t++) {
            const int nact = (t == 0) ? 8 : min(__ffs(t), 8);
            const int rows = nact << 7;
            const int slot = t & 1;

            float xnext = 0.f;
            if (t + 1 < SEQT)
                xnext = __ldg(xp + (size_t)(t + 1) * BATCH * HSZ + tid);

            // P1: h update for active rows; push to rank1's hin[slot]
            if (tid < rows) {
                const int i  = tid >> 7;
                const int rr = tid & 127;
                float v = xreg;
#pragma unroll
                for (int j = 0; j < 8; j++) {
                    float sv = s[((((j * (j + 1)) >> 1) + i) << 7) + rr];
                    if (j >= i) v += sv;
                }
                float hv = tanhf(v);
                h[tid] = hv;
                st_remote_f32(dynb + (((uint32_t)slot << 10) + tid) * 4u, 1, hv);
            }
            __syncthreads();                               // S1
            if (tid == 0) mbar_arrive_remote(barb + slot * 8, 1);  // h_ready[slot]

            // global W_hh pairs with j >= 2 (even steps with nact >= 3)
            if (nact >= 3) {
                const int P    = (nact * (nact + 1)) >> 1;
                const int outs = (P - 3) << 7;
                const int lane8 = tid & 7;
                for (int o = tid >> 3; o < outs; o += 128) {
                    const int p  = 3 + (o >> 7);
                    const int rr = o & 127;
                    const int i = spi[p], j = spj[p];
                    const float4* wrow = (const float4*)(Whh + (((size_t)((i << 7) + rr)) << 10) + (j << 7));
                    const float4* hb   = (const float4*)(h + (j << 7));
                    float v = 0.f;
#pragma unroll
                    for (int q = 0; q < 4; q++) {
                        float4 w4 = __ldg(wrow + q * 8 + lane8);
                        float4 h4 = hb[q * 8 + lane8];
                        v = fmaf(w4.x, h4.x, fmaf(w4.y, h4.y, fmaf(w4.z, h4.z, fmaf(w4.w, h4.w, v))));
                    }
                    v += __shfl_xor_sync(0xffffffffu, v, 4);
                    v += __shfl_xor_sync(0xffffffffu, v, 2);
                    v += __shfl_xor_sync(0xffffffffu, v, 1);
                    if (lane8 == 0) s[(p << 7) + rr] = v;
                }
            }

            // pinned smem pairs: (0,0) always; (0,1),(1,1) when module1 active
            {
                float4 h0 = ((const float4*)h)[lane];
                float4 h1 = make_float4(0.f, 0.f, 0.f, 0.f);
                const int ntask = (nact >= 2) ? 12 : 4;
                if (nact >= 2) h1 = ((const float4*)(h + 128))[lane];
                for (int k = 0; k < ntask; k++) {
                    int task = wid + (k << 5);
                    const float4* wr;
                    float4 hh;
                    float* dst;
                    if (task < 128)      { wr = (const float4*)W00 + (task << 5);          hh = h0; dst = s + task; }
                    else if (task < 256) { wr = (const float4*)W01 + ((task - 128) << 5);  hh = h1; dst = s + 128 + (task - 128); }
                    else                 { wr = (const float4*)W11 + ((task - 256) << 5);  hh = h1; dst = s + 256 + (task - 256); }
                    float4 w4 = wr[lane];
                    float v = fmaf(w4.x, hh.x, fmaf(w4.y, hh.y, fmaf(w4.z, hh.z, w4.w * hh.w)));
                    v += __shfl_xor_sync(0xffffffffu, v, 16);
                    v += __shfl_xor_sync(0xffffffffu, v, 8);
                    v += __shfl_xor_sync(0xffffffffu, v, 4);
                    v += __shfl_xor_sync(0xffffffffu, v, 2);
                    v += __shfl_xor_sync(0xffffffffu, v, 1);
                    if (lane == 0) *dst = v;
                }
            }

            // backpressure: before step t+1 writes hin[(t+1)&1], make sure
            // rank1 released it (its use at step t-1)
            if (tid == 0) {
                int tn = t + 1;
                if (tn >= 2 && tn < SEQT) {
                    int k = tn >> 1;
                    mbar_wait_acq(barb + 16 + (tn & 1) * 8, (uint32_t)((k - 1) & 1));
                }
            }
            __syncthreads();                               // S2
            xreg = xnext;
        }
    } else {
        // ================= output CTA =================
        float* hin = dyn;              // [2][1024]
        float* c   = dyn + 2048;       // [8][256]
        float* FC0 = dyn + 4096;       // [256][128]
        float* ob  = out + (size_t)b * SEQT * ISZ;

        for (int t = 0; t < SEQT; t++) {
            const int nact = (t == 0) ? 8 : min(__ffs(t), 8);
            const int slot = t & 1;

            if (tid == 0) mbar_wait_acq(barb + slot * 8, (uint32_t)((t >> 1) & 1));
            __syncthreads();           // h ready in hin[slot]
            const float* hs = hin + (slot << 10);

            // global fc blocks m >= 1 (even steps)
            if (nact >= 2) {
                const int outs = (nact - 1) << 8;
                const int lane8 = tid & 7;
                for (int o = tid >> 3; o < outs; o += 128) {
                    const int m  = 1 + (o >> 8);
                    const int oo = o & 255;
                    const float4* wrow = (const float4*)(fcw + (((size_t)oo) << 10) + (m << 7));
                    const float4* hb   = (const float4*)(hs + (m << 7));
                    float v = 0.f;
#pragma unroll
                    for (int q = 0; q < 4; q++) {
                        float4 w4 = __ldg(wrow + q * 8 + lane8);
                        float4 h4 = hb[q * 8 + lane8];
                        v = fmaf(w4.x, h4.x, fmaf(w4.y, h4.y, fmaf(w4.z, h4.z, fmaf(w4.w, h4.w, v))));
                    }
                    v += __shfl_xor_sync(0xffffffffu, v, 4);
                    v += __shfl_xor_sync(0xffffffffu, v, 2);
                    v += __shfl_xor_sync(0xffffffffu, v, 1);
                    if (lane8 == 0) c[(m << 8) + oo] = v;
                }
            }

            // pinned FC0 matvec (every step): 256 outputs, warp-per-output
            {
                float4 h0 = ((const float4*)hs)[lane];
#pragma unroll
                for (int k = 0; k < 8; k++) {
                    int oo = wid + (k << 5);
                    float4 w4 = ((const float4*)FC0)[(oo << 5) + lane];
                    float v = fmaf(w4.x, h0.x, fmaf(w4.y, h0.y, fmaf(w4.z, h0.z, w4.w * h0.w)));
                    v += __shfl_xor_sync(0xffffffffu, v, 16);
                    v += __shfl_xor_sync(0xffffffffu, v, 8);
                    v += __shfl_xor_sync(0xffffffffu, v, 4);
                    v += __shfl_xor_sync(0xffffffffu, v, 2);
                    v += __shfl_xor_sync(0xffffffffu, v, 1);
                    if (lane == 0) c[oo] = v;
                }
            }
            __syncthreads();           // c ready; hin[slot] consumed
            if (tid == 0) mbar_arrive_remote(barb + 16 + slot * 8, 0);  // slot_free[slot]

            // y[t] = sum_m c[m] + fc_b
            if (tid < ISZ) {
                float v = __ldg(fcb + tid);
#pragma unroll
                for (int m = 0; m < 8; m++) v += c[(m << 8) + tid];
                ob[(size_t)t * ISZ + tid] = v;
            }
        }
    }

    cluster_sync_();   // no CTA exits while peer may still touch its smem
}

// ---------------------------------------------------------------------------
extern "C" void kernel_launch(void* const* d_in, const int* in_sizes, int n_in,
                              void* d_out, int out_size)
{
    const float* x   = (const float*)d_in[0];
    const float* wih = (const float*)d_in[1];
    const float* whh = (const float*)d_in[2];
    const float* bih = (const float*)d_in[3];
    const float* bhh = (const float*)d_in[4];
    const float* fcw = (const float*)d_in[5];
    const float* fcb = (const float*)d_in[6];
    float* out = (float*)d_out;

    cudaFuncSetAttribute(cwrnn, cudaFuncAttributeMaxDynamicSharedMemorySize, CW_SMEM_BYTES);

    dim3 ggrid((BATCH * SEQT) / 128, HSZ / 128);
    xproj_gemm<<<ggrid, 256>>>(x, wih, bih, bhh);
    cwrnn<<<2 * BATCH, 1024, CW_SMEM_BYTES>>>(whh, fcw, fcb, out);
}

// round 6
// speedup vs baseline: 7.3980x; 1.0954x over previous
#include <cuda_runtime.h>
#include <math.h>
#include <stdint.h>

#define BATCH 64
#define SEQT  2048
#define ISZ   256
#define HSZ   1024

// 512 MB scratch for the precomputed input projection, laid out [t][b][h]
static __device__ float g_xproj[(size_t)SEQT * BATCH * HSZ];

// ---------------------------------------------------------------------------
// Kernel 1: xproj[t][b][:] = x[b][t][:] @ W_ih^T + (b_ih + b_hh)
// 128x128x32 fp32 SGEMM. M = B*T = 131072, N = H = 1024, K = 256.
// ---------------------------------------------------------------------------
__global__ __launch_bounds__(256, 2)
void xproj_gemm(const float* __restrict__ X, const float* __restrict__ Wih,
                const float* __restrict__ bih, const float* __restrict__ bhh)
{
    __shared__ float As[32][132];
    __shared__ float Bs[32][132];

    const int bm = blockIdx.x;
    const int bn = blockIdx.y;
    const int tid = threadIdx.x;
    const int tx = tid & 15;
    const int ty = tid >> 4;

    float acc[8][8];
#pragma unroll
    for (int i = 0; i < 8; i++)
#pragma unroll
        for (int j = 0; j < 8; j++) acc[i][j] = 0.f;

    const float* Ab = X   + (size_t)bm * 128 * ISZ;
    const float* Bb = Wih + (size_t)bn * 128 * ISZ;
    const int lr = tid >> 3;
    const int lc = (tid & 7) << 2;

    for (int k0 = 0; k0 < ISZ; k0 += 32) {
#pragma unroll
        for (int q = 0; q < 4; q++) {
            int row = lr + q * 32;
            float4 va = *(const float4*)(Ab + (size_t)row * ISZ + k0 + lc);
            As[lc + 0][row] = va.x; As[lc + 1][row] = va.y;
            As[lc + 2][row] = va.z; As[lc + 3][row] = va.w;
            float4 vb = *(const float4*)(Bb + (size_t)row * ISZ + k0 + lc);
            Bs[lc + 0][row] = vb.x; Bs[lc + 1][row] = vb.y;
            Bs[lc + 2][row] = vb.z; Bs[lc + 3][row] = vb.w;
        }
        __syncthreads();
#pragma unroll
        for (int kk = 0; kk < 32; kk++) {
            float a[8], bb[8];
            float4 a0 = *(const float4*)&As[kk][ty * 8];
            float4 a1 = *(const float4*)&As[kk][ty * 8 + 4];
            float4 b0 = *(const float4*)&Bs[kk][tx * 8];
            float4 b1 = *(const float4*)&Bs[kk][tx * 8 + 4];
            a[0] = a0.x; a[1] = a0.y; a[2] = a0.z; a[3] = a0.w;
            a[4] = a1.x; a[5] = a1.y; a[6] = a1.z; a[7] = a1.w;
            bb[0] = b0.x; bb[1] = b0.y; bb[2] = b0.z; bb[3] = b0.w;
            bb[4] = b1.x; bb[5] = b1.y; bb[6] = b1.z; bb[7] = b1.w;
#pragma unroll
            for (int i = 0; i < 8; i++)
#pragma unroll
                for (int j = 0; j < 8; j++)
                    acc[i][j] = fmaf(a[i], bb[j], acc[i][j]);
        }
        __syncthreads();
    }

    const int colbase = bn * 128 + tx * 8;
    float bsum[8];
#pragma unroll
    for (int j = 0; j < 8; j++)
        bsum[j] = __ldg(bih + colbase + j) + __ldg(bhh + colbase + j);

#pragma unroll
    for (int i = 0; i < 8; i++) {
        int row = bm * 128 + ty * 8 + i;
        int tt  = row & (SEQT - 1);
        int bb2 = row >> 11;
        float* cr = g_xproj + ((size_t)tt * BATCH + bb2) * HSZ + colbase;
        float4 v0, v1;
        v0.x = acc[i][0] + bsum[0]; v0.y = acc[i][1] + bsum[1];
        v0.z = acc[i][2] + bsum[2]; v0.w = acc[i][3] + bsum[3];
        v1.x = acc[i][4] + bsum[4]; v1.y = acc[i][5] + bsum[5];
        v1.z = acc[i][6] + bsum[6]; v1.w = acc[i][7] + bsum[7];
        *(float4*)cr       = v0;
        *(float4*)(cr + 4) = v1;
    }
}

// ---------------------------------------------------------------------------
// Cluster/mbarrier helpers
// ---------------------------------------------------------------------------
__device__ __forceinline__ uint32_t smem_u32(const void* p) {
    uint32_t a;
    asm("{ .reg .u64 t; cvta.to.shared.u64 t, %1; cvt.u32.u64 %0, t; }" : "=r"(a) : "l"(p));
    return a;
}
__device__ __forceinline__ void mbar_init(uint32_t a, uint32_t cnt) {
    asm volatile("mbarrier.init.shared.b64 [%0], %1;" :: "r"(a), "r"(cnt) : "memory");
}
__device__ __forceinline__ void mbar_wait_acq(uint32_t a, uint32_t parity) {
    asm volatile(
        "{\n\t.reg .pred P;\n\t"
        "W_%=:\n\t"
        "mbarrier.try_wait.parity.acquire.cluster.shared::cta.b64 P, [%0], %1, 0x989680;\n\t"
        "@!P bra W_%=;\n\t}"
        :: "r"(a), "r"(parity) : "memory");
}
__device__ __forceinline__ void mbar_arrive_remote(uint32_t local_a, uint32_t rank) {
    asm volatile(
        "{\n\t.reg .b32 ra;\n\t"
        "mapa.shared::cluster.u32 ra, %0, %1;\n\t"
        "mbarrier.arrive.release.cluster.shared::cluster.b64 _, [ra];\n\t}"
        :: "r"(local_a), "r"(rank) : "memory");
}
__device__ __forceinline__ void st_remote_f32(uint32_t local_a, uint32_t rank, float v) {
    asm volatile(
        "{\n\t.reg .b32 ra;\n\t"
        "mapa.shared::cluster.u32 ra, %0, %1;\n\t"
        "st.shared::cluster.f32 [ra], %2;\n\t}"
        :: "r"(local_a), "r"(rank), "f"(v) : "memory");
}
__device__ __forceinline__ void fence_cluster_() {
    asm volatile("fence.acq_rel.cluster;" ::: "memory");
}
__device__ __forceinline__ void cluster_sync_() {
    asm volatile("barrier.cluster.arrive.aligned;" ::: "memory");
    asm volatile("barrier.cluster.wait.aligned;" ::: "memory");
}

// ---------------------------------------------------------------------------
// Kernel 2: clockwork recurrence, cluster-of-2 per batch element, 512 threads.
//  rank0: W00,W01 in REGISTERS (64/thr), W11 in bank-interleaved SMEM,
//         j>=2 W_hh pairs from L2. Maintains h + s partials, pushes active
//         h rows to rank1 via DSMEM each step.
//  rank1: FC0 in REGISTERS (64/thr), FC1 in bank-interleaved SMEM, fc m>=2
//         from L2. Computes y[t] off the critical path.
// 8-lane-group dot products: lane = (g,s8), g=lane>>3, s8=lane&7; each
// output's 128-dot split as 8 sublanes x 4 float4; reduce = 3 shfl.
// SMEM weight layout interleave: chunk col4=s8*4+q stored at slot q*8+s8
// within each 32-float4 row -> conflict-free quarter-warp LDS.128.
// ---------------------------------------------------------------------------
#define CW_SMEM_BYTES ((2048 + 2048 + 256*128) * 4)   // rank1 layout is max: 147456

__global__ __launch_bounds__(512, 1) __cluster_dims__(2, 1, 1)
void cwrnn(const float* __restrict__ Whh, const float* __restrict__ fcw,
           const float* __restrict__ fcb, float* __restrict__ out)
{
    extern __shared__ float dyn[];
    __shared__ __align__(8) unsigned long long bars[4]; // [0..1]=h_ready, [2..3]=slot_free
    __shared__ unsigned char spi[36], spj[36];

    const int tid  = threadIdx.x;
    const int wid  = tid >> 5;
    const int lane = tid & 31;
    const int g    = lane >> 3;
    const int s8   = lane & 7;
    const uint32_t rank = blockIdx.x & 1;
    const int b = blockIdx.x >> 1;
    const uint32_t dynb = smem_u32(dyn);
    const uint32_t barb = smem_u32(bars);

    if (tid == 0) {
        mbar_init(barb + 0, 1);
        mbar_init(barb + 8, 1);
        mbar_init(barb + 16, 1);
        mbar_init(barb + 24, 1);
        int p = 0;
        for (int j = 0; j < 8; j++)
            for (int i = 0; i <= j; i++) { spi[p] = (unsigned char)i; spj[p] = (unsigned char)j; p++; }
    }

    if (rank == 0) {
        // ================= recurrence CTA =================
        float* h    = dyn;                 // [1024]
        float* s    = dyn + 1024;          // [36*128]
        float* W11s = s + 36 * 128;        // [128*128] interleaved

        const int outA = (wid << 3) + (g << 1);   // 2 outputs per thread-group
        float4 w00r[2][4], w01r[2][4];
#pragma unroll
        for (int o = 0; o < 2; o++)
#pragma unroll
            for (int q = 0; q < 4; q++) {
                w00r[o][q] = __ldg((const float4*)(Whh + (size_t)(outA + o) * HSZ) + (s8 * 4 + q));
                w01r[o][q] = __ldg((const float4*)(Whh + (size_t)(outA + o) * HSZ) + 32 + (s8 * 4 + q));
            }
        // W11 (rows 128..255, cols 128..255) into interleaved smem
        for (int idx = tid; idx < 4096; idx += 512) {
            int r = idx >> 5, c4 = idx & 31;
            int p = ((c4 & 3) << 3) + (c4 >> 2);
            ((float4*)W11s)[(r << 5) + p] =
                __ldg((const float4*)(Whh + (size_t)(128 + r) * HSZ) + 32 + c4);
        }
        for (int k = tid; k < 1024 + 36 * 128; k += 512) dyn[k] = 0.f;  // h, s
        __syncthreads();
        cluster_sync_();

        const float* xp = g_xproj + (size_t)b * HSZ;
        float xr0 = __ldg(xp + tid);
        float xr1 = __ldg(xp + 512 + tid);

        for (int t = 0; t < SEQT; t++) {
            const int nact = (t == 0) ? 8 : min(__ffs(t), 8);
            const int rows = nact << 7;
            const int slot = t & 1;
            const int tn = t + 1;

            // conditional prefetch of next step's xproj (only active rows)
            float xn0 = 0.f, xn1 = 0.f;
            if (tn < SEQT) {
                const int rn = min(__ffs(tn), 8) << 7;
                const float* xpn = xp + (size_t)tn * (BATCH * HSZ);
                if (tid < rn)       xn0 = __ldg(xpn + tid);
                if (tid + 512 < rn) xn1 = __ldg(xpn + 512 + tid);
            }

            // ---- P1: h update from cached partials; push to rank1 ----
            if (tid < rows) {
                const int i = tid >> 7, rr = tid & 127;
                float v = xr0;
#pragma unroll
                for (int j = 0; j < 8; j++) {
                    float sv = s[((((j * (j + 1)) >> 1) + i) << 7) + rr];
                    if (j >= i) v += sv;
                }
                float hv = tanhf(v);
                h[tid] = hv;
                st_remote_f32(dynb + (uint32_t)((slot << 10) + tid) * 4u, 1, hv);
            }
            if (tid + 512 < rows) {
                const int r = tid + 512;
                const int i = r >> 7, rr = r & 127;
                float v = xr1;
#pragma unroll
                for (int j = 0; j < 8; j++) {
                    float sv = s[((((j * (j + 1)) >> 1) + i) << 7) + rr];
                    if (j >= i) v += sv;
                }
                float hv = tanhf(v);
                h[r] = hv;
                st_remote_f32(dynb + (uint32_t)((slot << 10) + r) * 4u, 1, hv);
            }
            __syncthreads();                                  // S1: h + pushes done
            if (tid == 0) {
                fence_cluster_();
                mbar_arrive_remote(barb + slot * 8, 1);       // h_ready[slot]
            }

            // ---- L2 phase: W_hh pairs p >= 3 (j >= 2) ----
            if (nact >= 3) {
                const int P = (nact * (nact + 1)) >> 1;
                const int outs = (P - 3) << 7;
                for (int o = tid >> 3; o < outs; o += 64) {
                    const int p = 3 + (o >> 7);
                    const int rr = o & 127;
                    const int i = spi[p], j = spj[p];
                    const float4* wrow = (const float4*)(Whh + (((size_t)((i << 7) + rr)) << 10) + (j << 7));
                    const float4* hb   = (const float4*)(h + (j << 7));
                    float v = 0.f;
#pragma unroll
                    for (int q = 0; q < 4; q++) {
                        float4 w4 = __ldg(wrow + q * 8 + s8);
                        float4 h4 = hb[q * 8 + s8];
                        v = fmaf(w4.x, h4.x, fmaf(w4.y, h4.y, fmaf(w4.z, h4.z, fmaf(w4.w, h4.w, v))));
                    }
                    v += __shfl_xor_sync(0xffffffffu, v, 4);
                    v += __shfl_xor_sync(0xffffffffu, v, 2);
                    v += __shfl_xor_sync(0xffffffffu, v, 1);
                    if (s8 == 0) s[(p << 7) + rr] = v;
                }
            }

            // ---- even steps: W01 (regs) + W11 (smem) vs h[128:256] ----
            if (nact >= 2) {
                float4 hB[4];
#pragma unroll
                for (int q = 0; q < 4; q++) hB[q] = ((const float4*)(h + 128))[s8 * 4 + q];
#pragma unroll
                for (int o = 0; o < 2; o++) {
                    float v = 0.f;
#pragma unroll
                    for (int q = 0; q < 4; q++) {
                        float4 w4 = w01r[o][q];
                        v = fmaf(w4.x, hB[q].x, fmaf(w4.y, hB[q].y, fmaf(w4.z, hB[q].z, fmaf(w4.w, hB[q].w, v))));
                    }
                    v += __shfl_xor_sync(0xffffffffu, v, 4);
                    v += __shfl_xor_sync(0xffffffffu, v, 2);
                    v += __shfl_xor_sync(0xffffffffu, v, 1);
                    if (s8 == 0) s[128 + outA + o] = v;
                }
#pragma unroll
                for (int o = 0; o < 2; o++) {
                    float v = 0.f;
#pragma unroll
                    for (int q = 0; q < 4; q++) {
                        float4 w4 = ((const float4*)W11s)[((outA + o) << 5) + (q << 3) + s8];
                        v = fmaf(w4.x, hB[q].x, fmaf(w4.y, hB[q].y, fmaf(w4.z, hB[q].z, fmaf(w4.w, hB[q].w, v))));
                    }
                    v += __shfl_xor_sync(0xffffffffu, v, 4);
                    v += __shfl_xor_sync(0xffffffffu, v, 2);
                    v += __shfl_xor_sync(0xffffffffu, v, 1);
                    if (s8 == 0) s[256 + outA + o] = v;
                }
            }

            // ---- every step: W00 (regs) vs h[0:128] ----
            {
                float4 hA[4];
#pragma unroll
                for (int q = 0; q < 4; q++) hA[q] = ((const float4*)h)[s8 * 4 + q];
#pragma unroll
                for (int o = 0; o < 2; o++) {
                    float v = 0.f;
#pragma unroll
                    for (int q = 0; q < 4; q++) {
                        float4 w4 = w00r[o][q];
                        v = fmaf(w4.x, hA[q].x, fmaf(w4.y, hA[q].y, fmaf(w4.z, hA[q].z, fmaf(w4.w, hA[q].w, v))));
                    }
                    v += __shfl_xor_sync(0xffffffffu, v, 4);
                    v += __shfl_xor_sync(0xffffffffu, v, 2);
                    v += __shfl_xor_sync(0xffffffffu, v, 1);
                    if (s8 == 0) s[outA + o] = v;
                }
            }

            // backpressure: slot (t+1)&1 must be released by rank1
            if (tid == 0 && tn >= 2 && tn < SEQT) {
                mbar_wait_acq(barb + 16 + (tn & 1) * 8, (uint32_t)(((tn >> 1) - 1) & 1));
            }
            __syncthreads();                                  // S2: s ready
            xr0 = xn0; xr1 = xn1;
        }
    } else {
        // ================= output CTA =================
        float* hin  = dyn;              // [2][1024]
        float* c    = dyn + 2048;       // [8][256]
        float* FC1s = dyn + 4096;       // [256*128] interleaved

        const int outF = (wid << 4) + (g << 2);   // 4 outputs per thread-group
        float4 fc0r[4][4];
#pragma unroll
        for (int o = 0; o < 4; o++)
#pragma unroll
            for (int q = 0; q < 4; q++)
                fc0r[o][q] = __ldg((const float4*)(fcw + (size_t)(outF + o) * HSZ) + (s8 * 4 + q));
        // FC1 (all 256 rows, cols 128..255) into interleaved smem
        for (int idx = tid; idx < 8192; idx += 512) {
            int r = idx >> 5, c4 = idx & 31;
            int p = ((c4 & 3) << 3) + (c4 >> 2);
            ((float4*)FC1s)[(r << 5) + p] =
                __ldg((const float4*)(fcw + (size_t)r * HSZ) + 32 + c4);
        }
        __syncthreads();
        cluster_sync_();

        float* ob = out + (size_t)b * SEQT * ISZ;

        for (int t = 0; t < SEQT; t++) {
            const int nact = (t == 0) ? 8 : min(__ffs(t), 8);
            const int slot = t & 1;

            if (tid == 0) mbar_wait_acq(barb + slot * 8, (uint32_t)((t >> 1) & 1));
            __syncthreads();               // hin[slot] ready
            const float* hs = hin + (slot << 10);

            // ---- L2 phase: fc blocks m >= 2 ----
            if (nact >= 3) {
                const int outs = (nact - 2) << 8;
                for (int o = tid >> 3; o < outs; o += 64) {
                    const int m  = 2 + (o >> 8);
                    const int oo = o & 255;
                    const float4* wrow = (const float4*)(fcw + ((size_t)oo << 10) + (m << 7));
                    const float4* hb   = (const float4*)(hs + (m << 7));
                    float v = 0.f;
#pragma unroll
                    for (int q = 0; q < 4; q++) {
                        float4 w4 = __ldg(wrow + q * 8 + s8);
                        float4 h4 = hb[q * 8 + s8];
                        v = fmaf(w4.x, h4.x, fmaf(w4.y, h4.y, fmaf(w4.z, h4.z, fmaf(w4.w, h4.w, v))));
                    }
                    v += __shfl_xor_sync(0xffffffffu, v, 4);
                    v += __shfl_xor_sync(0xffffffffu, v, 2);
                    v += __shfl_xor_sync(0xffffffffu, v, 1);
                    if (s8 == 0) c[(m << 8) + oo] = v;
                }
            }

            // ---- even steps: FC1 (smem) vs hs[128:256] ----
            if (nact >= 2) {
                float4 hB[4];
#pragma unroll
                for (int q = 0; q < 4; q++) hB[q] = ((const float4*)(hs + 128))[s8 * 4 + q];
#pragma unroll
                for (int o = 0; o < 4; o++) {
                    float v = 0.f;
#pragma unroll
                    for (int q = 0; q < 4; q++) {
                        float4 w4 = ((const float4*)FC1s)[((outF + o) << 5) + (q << 3) + s8];
                        v = fmaf(w4.x, hB[q].x, fmaf(w4.y, hB[q].y, fmaf(w4.z, hB[q].z, fmaf(w4.w, hB[q].w, v))));
                    }
                    v += __shfl_xor_sync(0xffffffffu, v, 4);
                    v += __shfl_xor_sync(0xffffffffu, v, 2);
                    v += __shfl_xor_sync(0xffffffffu, v, 1);
                    if (s8 == 0) c[256 + outF + o] = v;
                }
            }

            // ---- every step: FC0 (regs) vs hs[0:128] ----
            {
                float4 hA[4];
#pragma unroll
                for (int q = 0; q < 4; q++) hA[q] = ((const float4*)hs)[s8 * 4 + q];
#pragma unroll
                for (int o = 0; o < 4; o++) {
                    float v = 0.f;
#pragma unroll
                    for (int q = 0; q < 4; q++) {
                        float4 w4 = fc0r[o][q];
                        v = fmaf(w4.x, hA[q].x, fmaf(w4.y, hA[q].y, fmaf(w4.z, hA[q].z, fmaf(w4.w, hA[q].w, v))));
                    }
                    v += __shfl_xor_sync(0xffffffffu, v, 4);
                    v += __shfl_xor_sync(0xffffffffu, v, 2);
                    v += __shfl_xor_sync(0xffffffffu, v, 1);
                    if (s8 == 0) c[outF + o] = v;
                }
            }
            __syncthreads();               // c ready; hin[slot] consumed
            if (tid == 0) {
                fence_cluster_();
                mbar_arrive_remote(barb + 16 + slot * 8, 0);  // slot_free[slot]
            }

            // ---- y[t] = sum_m c[m] + fc_b ----
            if (tid < ISZ) {
                float v = __ldg(fcb + tid);
#pragma unroll
                for (int m = 0; m < 8; m++) v += c[(m << 8) + tid];
                ob[(size_t)t * ISZ + tid] = v;
            }
        }
    }

    cluster_sync_();   // no CTA exits while peer may still touch its smem
}

// ---------------------------------------------------------------------------
extern "C" void kernel_launch(void* const* d_in, const int* in_sizes, int n_in,
                              void* d_out, int out_size)
{
    const float* x   = (const float*)d_in[0];
    const float* wih = (const float*)d_in[1];
    const float* whh = (const float*)d_in[2];
    const float* bih = (const float*)d_in[3];
    const float* bhh = (const float*)d_in[4];
    const float* fcw = (const float*)d_in[5];
    const float* fcb = (const float*)d_in[6];
    float* out = (float*)d_out;

    cudaFuncSetAttribute(cwrnn, cudaFuncAttributeMaxDynamicSharedMemorySize, CW_SMEM_BYTES);

    dim3 ggrid((BATCH * SEQT) / 128, HSZ / 128);
    xproj_gemm<<<ggrid, 256>>>(x, wih, bih, bhh);
    cwrnn<<<2 * BATCH, 512, CW_SMEM_BYTES>>>(whh, fcw, fcb, out);
}

// round 7
// speedup vs baseline: 7.7785x; 1.0514x over previous
#include <cuda_runtime.h>
#include <math.h>
#include <stdint.h>

#define BATCH 64
#define SEQT  2048
#define ISZ   256
#define HSZ   1024

// 512 MB scratch for the precomputed input projection, laid out [t][b][h]
static __device__ float g_xproj[(size_t)SEQT * BATCH * HSZ];

// ---------------------------------------------------------------------------
// Kernel 1: xproj[t][b][:] = x[b][t][:] @ W_ih^T + (b_ih + b_hh)
// TF32 tensor-core GEMM with 3-term split (fp32-accurate):
//   a*b ~= ah*bh + ah*bl + al*bh   (ah = tf32(a), al = tf32(a - ah))
// M = 131072, N = 1024, K = 256. CTA tile 128x128, 8 warps (4Mx2N),
// warp tile 32x64 via mma.sync.m16n8k8.row.col.f32.tf32.tf32.f32.
// ---------------------------------------------------------------------------
__device__ __forceinline__ uint32_t f32_to_tf32(float x) {
    uint32_t r;
    asm("cvt.rna.tf32.f32 %0, %1;" : "=r"(r) : "f"(x));
    return r;
}
__device__ __forceinline__ void mma_tf32(float4& d, const uint32_t a[4],
                                         const uint32_t b0, const uint32_t b1) {
    asm volatile(
        "mma.sync.aligned.m16n8k8.row.col.f32.tf32.tf32.f32 "
        "{%0,%1,%2,%3}, {%4,%5,%6,%7}, {%8,%9}, {%0,%1,%2,%3};"
        : "+f"(d.x), "+f"(d.y), "+f"(d.z), "+f"(d.w)
        : "r"(a[0]), "r"(a[1]), "r"(a[2]), "r"(a[3]), "r"(b0), "r"(b1));
}

// smem stage: Ah[8][132] | Al[8][132] | Bh[8][132] | Bl[8][132]  (4224 floats)
#define GST 4224
#define GEMM_SMEM_BYTES (2 * GST * 4)

__global__ __launch_bounds__(256, 2)
void xproj_gemm_tf32(const float* __restrict__ X, const float* __restrict__ Wih,
                     const float* __restrict__ bih, const float* __restrict__ bhh)
{
    extern __shared__ float gsm[];
    const int bn = blockIdx.x;      // 0..7
    const int bm = blockIdx.y;      // 0..1023
    const int tid = threadIdx.x;
    const int wid = tid >> 5;
    const int lane = tid & 31;
    const int grp = lane >> 2;      // 0..7
    const int tig = lane & 3;       // 0..3
    const int warpRow = wid >> 1;   // 0..3  -> 32 rows
    const int warpCol = wid & 1;    // 0..1  -> 64 cols

    const int ldr = tid >> 1;          // 0..127 (row within tile)
    const int ldc = (tid & 1) << 2;    // 0 or 4 (k-offset within chunk)

    const float* Ag = X   + ((size_t)(bm * 128 + ldr)) * 256 + ldc;
    const float* Bg = Wih + ((size_t)(bn * 128 + ldr)) * 256 + ldc;

    float4 acc[2][8];
#pragma unroll
    for (int i = 0; i < 2; i++)
#pragma unroll
        for (int j = 0; j < 8; j++) acc[i][j] = make_float4(0.f, 0.f, 0.f, 0.f);

    // preload chunk 0 into stage 0
    {
        float4 av = *(const float4*)Ag;
        float4 bv = *(const float4*)Bg;
        float* s = gsm;
        const float a4[4] = {av.x, av.y, av.z, av.w};
        const float b4[4] = {bv.x, bv.y, bv.z, bv.w};
#pragma unroll
        for (int e = 0; e < 4; e++) {
            uint32_t hi = f32_to_tf32(a4[e]);
            float lo = a4[e] - __uint_as_float(hi);
            s[(ldc + e) * 132 + ldr]        = __uint_as_float(hi);
            s[1056 + (ldc + e) * 132 + ldr] = __uint_as_float(f32_to_tf32(lo));
            uint32_t bhi = f32_to_tf32(b4[e]);
            float blo = b4[e] - __uint_as_float(bhi);
            s[2112 + (ldc + e) * 132 + ldr] = __uint_as_float(bhi);
            s[3168 + (ldc + e) * 132 + ldr] = __uint_as_float(f32_to_tf32(blo));
        }
    }
    __syncthreads();

    const int m0 = warpRow * 32 + grp;     // + mt*16 (+8 inside frag)
    const int n0 = warpCol * 64 + grp;     // + nt*8

    for (int kc = 0; kc < 32; kc++) {
        const int cur = kc & 1;
        float4 av, bv;
        if (kc + 1 < 32) {
            av = *(const float4*)(Ag + (kc + 1) * 8);
            bv = *(const float4*)(Bg + (kc + 1) * 8);
        }
        const float* As_h = gsm + cur * GST;
        const float* As_l = As_h + 1056;
        const float* Bs_h = As_h + 2112;
        const float* Bs_l = As_h + 3168;

        uint32_t ah[2][4], al[2][4];
#pragma unroll
        for (int mt = 0; mt < 2; mt++) {
            const int r = m0 + mt * 16;
            ah[mt][0] = __float_as_uint(As_h[tig * 132 + r]);
            ah[mt][1] = __float_as_uint(As_h[tig * 132 + r + 8]);
            ah[mt][2] = __float_as_uint(As_h[(tig + 4) * 132 + r]);
            ah[mt][3] = __float_as_uint(As_h[(tig + 4) * 132 + r + 8]);
            al[mt][0] = __float_as_uint(As_l[tig * 132 + r]);
            al[mt][1] = __float_as_uint(As_l[tig * 132 + r + 8]);
            al[mt][2] = __float_as_uint(As_l[(tig + 4) * 132 + r]);
            al[mt][3] = __float_as_uint(As_l[(tig + 4) * 132 + r + 8]);
        }
#pragma unroll
        for (int nt = 0; nt < 8; nt++) {
            const int cn = n0 + nt * 8;
            uint32_t bh0 = __float_as_uint(Bs_h[tig * 132 + cn]);
            uint32_t bh1 = __float_as_uint(Bs_h[(tig + 4) * 132 + cn]);
            uint32_t bl0 = __float_as_uint(Bs_l[tig * 132 + cn]);
            uint32_t bl1 = __float_as_uint(Bs_l[(tig + 4) * 132 + cn]);
#pragma unroll
            for (int mt = 0; mt < 2; mt++) {
                mma_tf32(acc[mt][nt], al[mt], bh0, bh1);
                mma_tf32(acc[mt][nt], ah[mt], bl0, bl1);
                mma_tf32(acc[mt][nt], ah[mt], bh0, bh1);
            }
        }

        if (kc + 1 < 32) {
            float* s = gsm + ((kc + 1) & 1) * GST;
            const float a4[4] = {av.x, av.y, av.z, av.w};
            const float b4[4] = {bv.x, bv.y, bv.z, bv.w};
#pragma unroll
            for (int e = 0; e < 4; e++) {
                uint32_t hi = f32_to_tf32(a4[e]);
                float lo = a4[e] - __uint_as_float(hi);
                s[(ldc + e) * 132 + ldr]        = __uint_as_float(hi);
                s[1056 + (ldc + e) * 132 + ldr] = __uint_as_float(f32_to_tf32(lo));
                uint32_t bhi = f32_to_tf32(b4[e]);
                float blo = b4[e] - __uint_as_float(bhi);
                s[2112 + (ldc + e) * 132 + ldr] = __uint_as_float(bhi);
                s[3168 + (ldc + e) * 132 + ldr] = __uint_as_float(f32_to_tf32(blo));
            }
        }
        __syncthreads();
    }

    // epilogue: add bias, remap row bt=(b*T+t) -> xproj[t][b][:]
#pragma unroll
    for (int nt = 0; nt < 8; nt++) {
        const int col = bn * 128 + warpCol * 64 + nt * 8 + tig * 2;
        const float bs0 = __ldg(bih + col) + __ldg(bhh + col);
        const float bs1 = __ldg(bih + col + 1) + __ldg(bhh + col + 1);
#pragma unroll
        for (int mt = 0; mt < 2; mt++) {
            const int r0 = bm * 128 + warpRow * 32 + mt * 16 + grp;
            float4 d = acc[mt][nt];
            {
                int tt = r0 & (SEQT - 1), b2 = r0 >> 11;
                float2 v = make_float2(d.x + bs0, d.y + bs1);
                *(float2*)(g_xproj + ((size_t)tt * BATCH + b2) * HSZ + col) = v;
            }
            {
                int r1 = r0 + 8;
                int tt = r1 & (SEQT - 1), b2 = r1 >> 11;
                float2 v = make_float2(d.z + bs0, d.w + bs1);
                *(float2*)(g_xproj + ((size_t)tt * BATCH + b2) * HSZ + col) = v;
            }
        }
    }
}

// ---------------------------------------------------------------------------
// Cluster/mbarrier helpers
// ---------------------------------------------------------------------------
__device__ __forceinline__ uint32_t smem_u32(const void* p) {
    uint32_t a;
    asm("{ .reg .u64 t; cvta.to.shared.u64 t, %1; cvt.u32.u64 %0, t; }" : "=r"(a) : "l"(p));
    return a;
}
__device__ __forceinline__ void mbar_init(uint32_t a, uint32_t cnt) {
    asm volatile("mbarrier.init.shared.b64 [%0], %1;" :: "r"(a), "r"(cnt) : "memory");
}
__device__ __forceinline__ void mbar_wait_acq(uint32_t a, uint32_t parity) {
    asm volatile(
        "{\n\t.reg .pred P;\n\t"
        "W_%=:\n\t"
        "mbarrier.try_wait.parity.acquire.cluster.shared::cta.b64 P, [%0], %1, 0x989680;\n\t"
        "@!P bra W_%=;\n\t}"
        :: "r"(a), "r"(parity) : "memory");
}
__device__ __forceinline__ void mbar_arrive_remote(uint32_t local_a, uint32_t rank) {
    asm volatile(
        "{\n\t.reg .b32 ra;\n\t"
        "mapa.shared::cluster.u32 ra, %0, %1;\n\t"
        "mbarrier.arrive.release.cluster.shared::cluster.b64 _, [ra];\n\t}"
        :: "r"(local_a), "r"(rank) : "memory");
}
__device__ __forceinline__ void st_remote_f32(uint32_t local_a, uint32_t rank, float v) {
    asm volatile(
        "{\n\t.reg .b32 ra;\n\t"
        "mapa.shared::cluster.u32 ra, %0, %1;\n\t"
        "st.shared::cluster.f32 [ra], %2;\n\t}"
        :: "r"(local_a), "r"(rank), "f"(v) : "memory");
}
__device__ __forceinline__ void cluster_sync_() {
    asm volatile("barrier.cluster.arrive.aligned;" ::: "memory");
    asm volatile("barrier.cluster.wait.aligned;" ::: "memory");
}

// ---------------------------------------------------------------------------
// Kernel 2: clockwork recurrence, cluster-of-2 per batch element, 512 threads.
//  rank0: W00 in regs (32), W01/W11 in bank-interleaved SMEM; L2 phase only
//         for pairs (i<=1, j>=2). Maintains h + s, pushes active h to rank1.
//  rank1: FC0 in regs (64), FC1 interleaved SMEM, fc m>=2 from L2; ALSO owns
//         all Whh pairs with i>=2 (needed >= 4 steps later) and remote-stores
//         them into rank0's s. Computes y[t].
// No cluster fences: mbarrier release-arrive / acquire-wait order the DSMEM
// stores (producer pattern).
// ---------------------------------------------------------------------------
// rank0 smem: h[1024] | s[4608] | W01s[16384] | W11s[16384]  = 38400 floats
// rank1 smem: hin[2048] | c[2048] | FC1s[32768]              = 36864 floats
#define CW_SMEM_BYTES (38400 * 4)
#define S_OFF 1024   // offset of s[] in rank0's dyn layout (floats)

__global__ __launch_bounds__(512, 1) __cluster_dims__(2, 1, 1)
void cwrnn(const float* __restrict__ Whh, const float* __restrict__ fcw,
           const float* __restrict__ fcb, float* __restrict__ out)
{
    extern __shared__ float dyn[];
    __shared__ __align__(8) unsigned long long bars[4]; // [0..1]=h_ready, [2..3]=slot_free
    __shared__ unsigned char qi[21], qj[21];            // pairs with i>=2, j-major

    const int tid  = threadIdx.x;
    const int wid  = tid >> 5;
    const int lane = tid & 31;
    const int g    = lane >> 3;
    const int s8   = lane & 7;
    const uint32_t rank = blockIdx.x & 1;
    const int b = blockIdx.x >> 1;
    const uint32_t dynb = smem_u32(dyn);
    const uint32_t barb = smem_u32(bars);

    if (tid == 0) {
        mbar_init(barb + 0, 1);
        mbar_init(barb + 8, 1);
        mbar_init(barb + 16, 1);
        mbar_init(barb + 24, 1);
        int e = 0;
        for (int j = 2; j < 8; j++)
            for (int i = 2; i <= j; i++) { qi[e] = (unsigned char)i; qj[e] = (unsigned char)j; e++; }
    }

    if (rank == 0) {
        // ================= recurrence CTA =================
        float* h    = dyn;                    // [1024]
        float* s    = dyn + S_OFF;            // [36*128]
        float* W01s = s + 36 * 128;           // [128*128] interleaved
        float* W11s = W01s + 128 * 128;       // [128*128] interleaved

        const int outA = (wid << 3) + (g << 1);   // 2 outputs per 8-lane group
        float4 w00r[2][4];
#pragma unroll
        for (int o = 0; o < 2; o++)
#pragma unroll
            for (int q = 0; q < 4; q++)
                w00r[o][q] = __ldg((const float4*)(Whh + (size_t)(outA + o) * HSZ) + (s8 * 4 + q));

        for (int idx = tid; idx < 4096; idx += 512) {
            int r = idx >> 5, c4 = idx & 31;
            int p = ((c4 & 3) << 3) + (c4 >> 2);
            ((float4*)W01s)[(r << 5) + p] = __ldg((const float4*)(Whh + (size_t)r * HSZ) + 32 + c4);
            ((float4*)W11s)[(r << 5) + p] = __ldg((const float4*)(Whh + (size_t)(128 + r) * HSZ) + 32 + c4);
        }
        for (int k = tid; k < 1024 + 36 * 128; k += 512) dyn[k] = 0.f;  // h, s
        __syncthreads();
        cluster_sync_();

        const float* xp = g_xproj + (size_t)b * HSZ;
        float xr0 = __ldg(xp + tid);
        float xr1 = __ldg(xp + 512 + tid);

        for (int t = 0; t < SEQT; t++) {
            const int nact = (t == 0) ? 8 : min(__ffs(t), 8);
            const int rows = nact << 7;
            const int slot = t & 1;
            const int tn = t + 1;

            float xn0 = 0.f, xn1 = 0.f;
            if (tn < SEQT) {
                const int rn = min(__ffs(tn), 8) << 7;
                const float* xpn = xp + (size_t)tn * (BATCH * HSZ);
                if (tid < rn)       xn0 = __ldg(xpn + tid);
                if (tid + 512 < rn) xn1 = __ldg(xpn + 512 + tid);
            }

            // ---- P1: h update from cached partials; push to rank1 ----
            if (tid < rows) {
                const int i = tid >> 7, rr = tid & 127;
                float v = xr0, v2 = 0.f;
#pragma unroll
                for (int j = 0; j < 8; j++) {
                    float sv = s[((((j * (j + 1)) >> 1) + i) << 7) + rr];
                    if (j >= i) { if (j & 1) v2 += sv; else v += sv; }
                }
                float hv = tanhf(v + v2);
                h[tid] = hv;
                st_remote_f32(dynb + (uint32_t)((slot << 10) + tid) * 4u, 1, hv);
            }
            if (tid + 512 < rows) {
                const int r = tid + 512;
                const int i = r >> 7, rr = r & 127;
                float v = xr1, v2 = 0.f;
#pragma unroll
                for (int j = 0; j < 8; j++) {
                    float sv = s[((((j * (j + 1)) >> 1) + i) << 7) + rr];
                    if (j >= i) { if (j & 1) v2 += sv; else v += sv; }
                }
                float hv = tanhf(v + v2);
                h[r] = hv;
                st_remote_f32(dynb + (uint32_t)((slot << 10) + r) * 4u, 1, hv);
            }
            __syncthreads();                                  // S1
            if (tid == 0) mbar_arrive_remote(barb + slot * 8, 1);   // h_ready[slot]

            // ---- L2 phase: pairs (i<=1, j>=2), 2*(nact-2) blocks ----
            if (nact >= 3) {
                const int outs = ((nact - 2) << 1) << 7;
                for (int o = tid >> 3; o < outs; o += 64) {
                    const int e = o >> 7;
                    const int rr = o & 127;
                    const int j = 2 + (e >> 1);
                    const int i = e & 1;
                    const int p = ((j * (j + 1)) >> 1) + i;
                    const float4* wrow = (const float4*)(Whh + (((size_t)((i << 7) + rr)) << 10) + (j << 7));
                    const float4* hb   = (const float4*)(h + (j << 7));
                    float v = 0.f;
#pragma unroll
                    for (int q = 0; q < 4; q++) {
                        float4 w4 = __ldg(wrow + q * 8 + s8);
                        float4 h4 = hb[q * 8 + s8];
                        v = fmaf(w4.x, h4.x, fmaf(w4.y, h4.y, fmaf(w4.z, h4.z, fmaf(w4.w, h4.w, v))));
                    }
                    v += __shfl_xor_sync(0xffffffffu, v, 4);
                    v += __shfl_xor_sync(0xffffffffu, v, 2);
                    v += __shfl_xor_sync(0xffffffffu, v, 1);
                    if (s8 == 0) s[(p << 7) + rr] = v;
                }
            }

            // ---- even steps: W01/W11 (interleaved smem) vs h[128:256] ----
            if (nact >= 2) {
                float4 hB[4];
#pragma unroll
                for (int q = 0; q < 4; q++) hB[q] = ((const float4*)(h + 128))[s8 * 4 + q];
#pragma unroll
                for (int o = 0; o < 2; o++) {
                    float va = 0.f, vb = 0.f;
#pragma unroll
                    for (int q = 0; q < 4; q++) {
                        float4 wa = ((const float4*)W01s)[((outA + o) << 5) + (q << 3) + s8];
                        float4 wb = ((const float4*)W11s)[((outA + o) << 5) + (q << 3) + s8];
                        va = fmaf(wa.x, hB[q].x, fmaf(wa.y, hB[q].y, fmaf(wa.z, hB[q].z, fmaf(wa.w, hB[q].w, va))));
                        vb = fmaf(wb.x, hB[q].x, fmaf(wb.y, hB[q].y, fmaf(wb.z, hB[q].z, fmaf(wb.w, hB[q].w, vb))));
                    }
                    va += __shfl_xor_sync(0xffffffffu, va, 4);
                    va += __shfl_xor_sync(0xffffffffu, va, 2);
                    va += __shfl_xor_sync(0xffffffffu, va, 1);
                    vb += __shfl_xor_sync(0xffffffffu, vb, 4);
                    vb += __shfl_xor_sync(0xffffffffu, vb, 2);
                    vb += __shfl_xor_sync(0xffffffffu, vb, 1);
                    if (s8 == 0) { s[128 + outA + o] = va; s[256 + outA + o] = vb; }
                }
            }

            // ---- every step: W00 (regs) vs h[0:128] ----
            {
                float4 hA[4];
#pragma unroll
                for (int q = 0; q < 4; q++) hA[q] = ((const float4*)h)[s8 * 4 + q];
#pragma unroll
                for (int o = 0; o < 2; o++) {
                    float v = 0.f, v2 = 0.f;
                    v  = fmaf(w00r[o][0].x, hA[0].x, fmaf(w00r[o][0].y, hA[0].y, fmaf(w00r[o][0].z, hA[0].z, w00r[o][0].w * hA[0].w)));
                    v2 = fmaf(w00r[o][1].x, hA[1].x, fmaf(w00r[o][1].y, hA[1].y, fmaf(w00r[o][1].z, hA[1].z, w00r[o][1].w * hA[1].w)));
                    v  = fmaf(w00r[o][2].x, hA[2].x, fmaf(w00r[o][2].y, hA[2].y, fmaf(w00r[o][2].z, hA[2].z, fmaf(w00r[o][2].w, hA[2].w, v))));
                    v2 = fmaf(w00r[o][3].x, hA[3].x, fmaf(w00r[o][3].y, hA[3].y, fmaf(w00r[o][3].z, hA[3].z, fmaf(w00r[o][3].w, hA[3].w, v2))));
                    v += v2;
                    v += __shfl_xor_sync(0xffffffffu, v, 4);
                    v += __shfl_xor_sync(0xffffffffu, v, 2);
                    v += __shfl_xor_sync(0xffffffffu, v, 1);
                    if (s8 == 0) s[outA + o] = v;
                }
            }

            // backpressure: slot (t+1)&1 must have been released by rank1
            if (tid == 0 && tn >= 2 && tn < SEQT) {
                mbar_wait_acq(barb + 16 + (tn & 1) * 8, (uint32_t)(((tn >> 1) - 1) & 1));
            }
            __syncthreads();                                  // S2
            xr0 = xn0; xr1 = xn1;
        }
    } else {
        // ================= output CTA =================
        float* hin  = dyn;              // [2][1024]
        float* c    = dyn + 2048;       // [8][256]
        float* FC1s = dyn + 4096;       // [256*128] interleaved

        const int outF = (wid << 4) + (g << 2);   // 4 outputs per 8-lane group
        float4 fc0r[4][4];
#pragma unroll
        for (int o = 0; o < 4; o++)
#pragma unroll
            for (int q = 0; q < 4; q++)
                fc0r[o][q] = __ldg((const float4*)(fcw + (size_t)(outF + o) * HSZ) + (s8 * 4 + q));
        for (int idx = tid; idx < 8192; idx += 512) {
            int r = idx >> 5, c4 = idx & 31;
            int p = ((c4 & 3) << 3) + (c4 >> 2);
            ((float4*)FC1s)[(r << 5) + p] = __ldg((const float4*)(fcw + (size_t)r * HSZ) + 32 + c4);
        }
        __syncthreads();
        cluster_sync_();

        float* ob = out + (size_t)b * SEQT * ISZ;

        for (int t = 0; t < SEQT; t++) {
            const int nact = (t == 0) ? 8 : min(__ffs(t), 8);
            const int slot = t & 1;

            if (tid == 0) mbar_wait_acq(barb + slot * 8, (uint32_t)((t >> 1) & 1));
            __syncthreads();               // hin[slot] ready
            const float* hs = hin + (slot << 10);

            // ---- Whh pairs with i>=2 (for rank0, needed >= 4 steps later) ----
            if (nact >= 3) {
                const int TT = ((nact - 1) * (nact - 2)) >> 1;   // active entries
                const int outs = TT << 7;
                for (int o = tid >> 3; o < outs; o += 64) {
                    const int e  = o >> 7;
                    const int rr = o & 127;
                    const int i = qi[e], j = qj[e];
                    const int p = ((j * (j + 1)) >> 1) + i;
                    const float4* wrow = (const float4*)(Whh + (((size_t)((i << 7) + rr)) << 10) + (j << 7));
                    const float4* hb   = (const float4*)(hs + (j << 7));
                    float v = 0.f;
#pragma unroll
                    for (int q = 0; q < 4; q++) {
                        float4 w4 = __ldg(wrow + q * 8 + s8);
                        float4 h4 = hb[q * 8 + s8];
                        v = fmaf(w4.x, h4.x, fmaf(w4.y, h4.y, fmaf(w4.z, h4.z, fmaf(w4.w, h4.w, v))));
                    }
                    v += __shfl_xor_sync(0xffffffffu, v, 4);
                    v += __shfl_xor_sync(0xffffffffu, v, 2);
                    v += __shfl_xor_sync(0xffffffffu, v, 1);
                    if (s8 == 0)
                        st_remote_f32(dynb + (uint32_t)(S_OFF + (p << 7) + rr) * 4u, 0, v);
                }
            }

            // ---- L2 phase: fc blocks m >= 2 ----
            if (nact >= 3) {
                const int outs = (nact - 2) << 8;
                for (int o = tid >> 3; o < outs; o += 64) {
                    const int m  = 2 + (o >> 8);
                    const int oo = o & 255;
                    const float4* wrow = (const float4*)(fcw + ((size_t)oo << 10) + (m << 7));
                    const float4* hb   = (const float4*)(hs + (m << 7));
                    float v = 0.f;
#pragma unroll
                    for (int q = 0; q < 4; q++) {
                        float4 w4 = __ldg(wrow + q * 8 + s8);
                        float4 h4 = hb[q * 8 + s8];
                        v = fmaf(w4.x, h4.x, fmaf(w4.y, h4.y, fmaf(w4.z, h4.z, fmaf(w4.w, h4.w, v))));
                    }
                    v += __shfl_xor_sync(0xffffffffu, v, 4);
                    v += __shfl_xor_sync(0xffffffffu, v, 2);
                    v += __shfl_xor_sync(0xffffffffu, v, 1);
                    if (s8 == 0) c[(m << 8) + oo] = v;
                }
            }

            // ---- even steps: FC1 (interleaved smem) vs hs[128:256] ----
            if (nact >= 2) {
                float4 hB[4];
#pragma unroll
                for (int q = 0; q < 4; q++) hB[q] = ((const float4*)(hs + 128))[s8 * 4 + q];
#pragma unroll
                for (int o = 0; o < 4; o++) {
                    float v = 0.f;
#pragma unroll
                    for (int q = 0; q < 4; q++) {
                        float4 w4 = ((const float4*)FC1s)[((outF + o) << 5) + (q << 3) + s8];
                        v = fmaf(w4.x, hB[q].x, fmaf(w4.y, hB[q].y, fmaf(w4.z, hB[q].z, fmaf(w4.w, hB[q].w, v))));
                    }
                    v += __shfl_xor_sync(0xffffffffu, v, 4);
                    v += __shfl_xor_sync(0xffffffffu, v, 2);
                    v += __shfl_xor_sync(0xffffffffu, v, 1);
                    if (s8 == 0) c[256 + outF + o] = v;
                }
            }

            // ---- every step: FC0 (regs) vs hs[0:128] ----
            {
                float4 hA[4];
#pragma unroll
                for (int q = 0; q < 4; q++) hA[q] = ((const float4*)hs)[s8 * 4 + q];
#pragma unroll
                for (int o = 0; o < 4; o++) {
                    float v = 0.f, v2 = 0.f;
                    v  = fmaf(fc0r[o][0].x, hA[0].x, fmaf(fc0r[o][0].y, hA[0].y, fmaf(fc0r[o][0].z, hA[0].z, fc0r[o][0].w * hA[0].w)));
                    v2 = fmaf(fc0r[o][1].x, hA[1].x, fmaf(fc0r[o][1].y, hA[1].y, fmaf(fc0r[o][1].z, hA[1].z, fc0r[o][1].w * hA[1].w)));
                    v  = fmaf(fc0r[o][2].x, hA[2].x, fmaf(fc0r[o][2].y, hA[2].y, fmaf(fc0r[o][2].z, hA[2].z, fmaf(fc0r[o][2].w, hA[2].w, v))));
                    v2 = fmaf(fc0r[o][3].x, hA[3].x, fmaf(fc0r[o][3].y, hA[3].y, fmaf(fc0r[o][3].z, hA[3].z, fmaf(fc0r[o][3].w, hA[3].w, v2))));
                    v += v2;
                    v += __shfl_xor_sync(0xffffffffu, v, 4);
                    v += __shfl_xor_sync(0xffffffffu, v, 2);
                    v += __shfl_xor_sync(0xffffffffu, v, 1);
                    if (s8 == 0) c[outF + o] = v;
                }
            }
            __syncthreads();               // c ready; hin[slot] consumed; remote s done
            if (tid == 0) mbar_arrive_remote(barb + 16 + slot * 8, 0);  // slot_free[slot]

            // ---- y[t] = sum_m c[m] + fc_b ----
            if (tid < ISZ) {
                float v = __ldg(fcb + tid);
#pragma unroll
                for (int m = 0; m < 8; m++) v += c[(m << 8) + tid];
                ob[(size_t)t * ISZ + tid] = v;
            }
        }
    }

    cluster_sync_();   // no CTA exits while peer may still touch its smem
}

// ---------------------------------------------------------------------------
extern "C" void kernel_launch(void* const* d_in, const int* in_sizes, int n_in,
                              void* d_out, int out_size)
{
    const float* x   = (const float*)d_in[0];
    const float* wih = (const float*)d_in[1];
    const float* whh = (const float*)d_in[2];
    const float* bih = (const float*)d_in[3];
    const float* bhh = (const float*)d_in[4];
    const float* fcw = (const float*)d_in[5];
    const float* fcb = (const float*)d_in[6];
    float* out = (float*)d_out;

    cudaFuncSetAttribute(cwrnn, cudaFuncAttributeMaxDynamicSharedMemorySize, CW_SMEM_BYTES);

    dim3 ggrid(HSZ / 128, (BATCH * SEQT) / 128);
    xproj_gemm_tf32<<<ggrid, 256, GEMM_SMEM_BYTES>>>(x, wih, bih, bhh);
    cwrnn<<<2 * BATCH, 512, CW_SMEM_BYTES>>>(whh, fcw, fcb, out);
}

// round 8
// speedup vs baseline: 17.7078x; 2.2765x over previous
#include <cuda_runtime.h>
#include <math.h>
#include <stdint.h>

#define BATCH 64
#define SEQT  2048
#define ISZ   256
#define HSZ   1024

// ---------------------------------------------------------------------------
// Global scratch (module-compact layouts).
//  XP_m[k][b][128] : input projection at module-m active times (t = k<<m)
//  HT_m[k][b][128] : module-m hidden trajectory samples
//  U_j [k][b][128j]: Whh[0:128j, j-block] @ h_j^(k)  (contributions to m<j)
//  C_m [k][b][256] : fc_w[:, m-block] @ h_m^(k)
// ---------------------------------------------------------------------------
#define XP_TOT 33423360ull   // 8192 * 4080
#define U_TOT  32374784ull   // 8192 * 3952
#define C_TOT  66846720ull   // 16384 * 4080
static __device__ float g_xp[XP_TOT];
static __device__ float g_ht[XP_TOT];
static __device__ float g_u [U_TOT];
static __device__ float g_c [C_TOT];

__host__ __device__ constexpr size_t xpoff(int m) {
    return 8192ull * (size_t)(4096 - (4096 >> m));
}
__host__ __device__ constexpr size_t uoff(int j) {
    size_t s = 0;
    for (int p = 1; p < j; p++) s += (size_t)(2048 >> p) * 8192ull * (size_t)p;
    return s;
}
__host__ __device__ constexpr size_t coff(int m) {
    return 16384ull * (size_t)(4096 - (4096 >> m));
}

// ---------------------------------------------------------------------------
// Generic TF32 3-split GEMM:  C[M x N] = A[M x K] * Bm[N x K]^T   (fp32-accurate)
// grid = (N/128, M/128), 256 threads, 128x128 CTA tile, warp tile 32x64,
// mma.m16n8k8. amode=1: A rows gathered from x at t=(row>>6)<<mshift, b=row&63.
// ---------------------------------------------------------------------------
__device__ __forceinline__ uint32_t f32_to_tf32(float x) {
    uint32_t r;
    asm("cvt.rna.tf32.f32 %0, %1;" : "=r"(r) : "f"(x));
    return r;
}
__device__ __forceinline__ void mma_tf32(float4& d, const uint32_t a[4],
                                         const uint32_t b0, const uint32_t b1) {
    asm volatile(
        "mma.sync.aligned.m16n8k8.row.col.f32.tf32.tf32.f32 "
        "{%0,%1,%2,%3}, {%4,%5,%6,%7}, {%8,%9}, {%0,%1,%2,%3};"
        : "+f"(d.x), "+f"(d.y), "+f"(d.z), "+f"(d.w)
        : "r"(a[0]), "r"(a[1]), "r"(a[2]), "r"(a[3]), "r"(b0), "r"(b1));
}

#define GST 4224
#define GEMM_SMEM_BYTES (2 * GST * 4)

__global__ __launch_bounds__(256, 2)
void gemm_tf32(const float* __restrict__ A, const float* __restrict__ Bm,
               float* __restrict__ C, int K, int ldb, int ldc,
               int amode, int mshift)
{
    extern __shared__ float gsm[];
    const int bn = blockIdx.x;
    const int bm = blockIdx.y;
    const int tid = threadIdx.x;
    const int wid = tid >> 5;
    const int lane = tid & 31;
    const int grp = lane >> 2;
    const int tig = lane & 3;
    const int warpRow = wid >> 1;
    const int warpCol = wid & 1;

    const int ldr = tid >> 1;          // row within 128-tile
    const int ldk = (tid & 1) << 2;    // k offset (0 or 4) within chunk

    const int rowg = bm * 128 + ldr;
    size_t aoff;
    if (amode) aoff = ((size_t)(rowg & 63) * 2048 + (size_t)((rowg >> 6) << mshift)) * 256;
    else       aoff = (size_t)rowg * (size_t)K;
    const float* Ag = A + aoff + ldk;
    const float* Bg = Bm + (size_t)(bn * 128 + ldr) * (size_t)ldb + ldk;

    float4 acc[2][8];
#pragma unroll
    for (int i = 0; i < 2; i++)
#pragma unroll
        for (int j = 0; j < 8; j++) acc[i][j] = make_float4(0.f, 0.f, 0.f, 0.f);

    const int kchunks = K >> 3;

    // stage chunk 0
    {
        float4 av = *(const float4*)Ag;
        float4 bv = *(const float4*)Bg;
        float* s = gsm;
        const float a4[4] = {av.x, av.y, av.z, av.w};
        const float b4[4] = {bv.x, bv.y, bv.z, bv.w};
#pragma unroll
        for (int e = 0; e < 4; e++) {
            uint32_t hi = f32_to_tf32(a4[e]);
            float lo = a4[e] - __uint_as_float(hi);
            s[(ldk + e) * 132 + ldr]        = __uint_as_float(hi);
            s[1056 + (ldk + e) * 132 + ldr] = __uint_as_float(f32_to_tf32(lo));
            uint32_t bhi = f32_to_tf32(b4[e]);
            float blo = b4[e] - __uint_as_float(bhi);
            s[2112 + (ldk + e) * 132 + ldr] = __uint_as_float(bhi);
            s[3168 + (ldk + e) * 132 + ldr] = __uint_as_float(f32_to_tf32(blo));
        }
    }
    __syncthreads();

    const int m0 = warpRow * 32 + grp;
    const int n0 = warpCol * 64 + grp;

    for (int kc = 0; kc < kchunks; kc++) {
        const int cur = kc & 1;
        float4 av, bv;
        if (kc + 1 < kchunks) {
            av = *(const float4*)(Ag + (kc + 1) * 8);
            bv = *(const float4*)(Bg + (kc + 1) * 8);
        }
        const float* As_h = gsm + cur * GST;
        const float* As_l = As_h + 1056;
        const float* Bs_h = As_h + 2112;
        const float* Bs_l = As_h + 3168;

        uint32_t ah[2][4], al[2][4];
#pragma unroll
        for (int mt = 0; mt < 2; mt++) {
            const int r = m0 + mt * 16;
            ah[mt][0] = __float_as_uint(As_h[tig * 132 + r]);
            ah[mt][1] = __float_as_uint(As_h[tig * 132 + r + 8]);
            ah[mt][2] = __float_as_uint(As_h[(tig + 4) * 132 + r]);
            ah[mt][3] = __float_as_uint(As_h[(tig + 4) * 132 + r + 8]);
            al[mt][0] = __float_as_uint(As_l[tig * 132 + r]);
            al[mt][1] = __float_as_uint(As_l[tig * 132 + r + 8]);
            al[mt][2] = __float_as_uint(As_l[(tig + 4) * 132 + r]);
            al[mt][3] = __float_as_uint(As_l[(tig + 4) * 132 + r + 8]);
        }
#pragma unroll
        for (int nt = 0; nt < 8; nt++) {
            const int cn = n0 + nt * 8;
            uint32_t bh0 = __float_as_uint(Bs_h[tig * 132 + cn]);
            uint32_t bh1 = __float_as_uint(Bs_h[(tig + 4) * 132 + cn]);
            uint32_t bl0 = __float_as_uint(Bs_l[tig * 132 + cn]);
            uint32_t bl1 = __float_as_uint(Bs_l[(tig + 4) * 132 + cn]);
#pragma unroll
            for (int mt = 0; mt < 2; mt++) {
                mma_tf32(acc[mt][nt], al[mt], bh0, bh1);
                mma_tf32(acc[mt][nt], ah[mt], bl0, bl1);
                mma_tf32(acc[mt][nt], ah[mt], bh0, bh1);
            }
        }

        if (kc + 1 < kchunks) {
            float* s = gsm + ((kc + 1) & 1) * GST;
            const float a4[4] = {av.x, av.y, av.z, av.w};
            const float b4[4] = {bv.x, bv.y, bv.z, bv.w};
#pragma unroll
            for (int e = 0; e < 4; e++) {
                uint32_t hi = f32_to_tf32(a4[e]);
                float lo = a4[e] - __uint_as_float(hi);
                s[(ldk + e) * 132 + ldr]        = __uint_as_float(hi);
                s[1056 + (ldk + e) * 132 + ldr] = __uint_as_float(f32_to_tf32(lo));
                uint32_t bhi = f32_to_tf32(b4[e]);
                float blo = b4[e] - __uint_as_float(bhi);
                s[2112 + (ldk + e) * 132 + ldr] = __uint_as_float(bhi);
                s[3168 + (ldk + e) * 132 + ldr] = __uint_as_float(f32_to_tf32(blo));
            }
        }
        __syncthreads();
    }

    // epilogue: C[r][col]
#pragma unroll
    for (int nt = 0; nt < 8; nt++) {
        const int col = bn * 128 + warpCol * 64 + nt * 8 + tig * 2;
#pragma unroll
        for (int mt = 0; mt < 2; mt++) {
            const int r0 = bm * 128 + warpRow * 32 + mt * 16 + grp;
            float4 d = acc[mt][nt];
            *(float2*)(C + (size_t)r0 * ldc + col)       = make_float2(d.x, d.y);
            *(float2*)(C + (size_t)(r0 + 8) * ldc + col) = make_float2(d.z, d.w);
        }
    }
}

// ---------------------------------------------------------------------------
// Chain kernel (template on module index MM): sequential 128-dim recurrence.
//   h^(k) = tanh( XP_m[k] + bias_m + sum_{j>m} U_j[(t-1)>>j][m-slice] + Wmm @ h^(k-1) )
// One CTA per batch element, 256 threads (2 threads per output row, Wmm in regs,
// h broadcast from smem). Writes HT_m[k][b][128].
// ---------------------------------------------------------------------------
template<int MM>
__global__ __launch_bounds__(256, 1)
void chain_kernel(const float* __restrict__ Whh, const float* __restrict__ bih,
                  const float* __restrict__ bhh)
{
    const int b = blockIdx.x;
    const int tid = threadIdx.x;
    const int r = tid & 127;
    const int half = tid >> 7;

    // pinned diagonal block row-half in registers
    float4 w[16];
    const float4* wrow = (const float4*)(Whh + (size_t)(128 * MM + r) * 1024 + 128 * MM + 64 * half);
#pragma unroll
    for (int q = 0; q < 16; q++) w[q] = __ldg(wrow + q);

    float bsr = 0.f;
    if (half == 0) bsr = __ldg(bih + 128 * MM + r) + __ldg(bhh + 128 * MM + r);

    __shared__ __align__(16) float h[128];
    __shared__ float ps[128];
    if (tid < 128) h[tid] = 0.f;
    __syncthreads();

    constexpr int KS = 2048 >> MM;
    constexpr int NU = 7 - MM;
    const float* xp = g_xp + xpoff(MM) + (size_t)b * 128;
    float* ht = g_ht + xpoff(MM) + (size_t)b * 128;

    float zx = 0.f;
    float zu[NU > 0 ? NU : 1];
#pragma unroll
    for (int e = 0; e < NU; e++) zu[e] = 0.f;
    if (half == 0) zx = __ldg(xp + r);

    for (int k = 0; k < KS; k++) {
        float z = 0.f;
        if (half == 0) {
            z = zx + bsr;
            if (k > 0) {
#pragma unroll
                for (int e = 0; e < NU; e++) z += zu[e];
            }
        }
        // prefetch step k+1 inputs (consumed next iteration)
        if (half == 0 && k + 1 < KS) {
            zx = __ldg(xp + (size_t)(k + 1) * 8192 + r);
            const int tm1 = ((k + 1) << MM) - 1;
#pragma unroll
            for (int e = 0; e < NU; e++) {
                const int j = MM + 1 + e;
                const size_t base = uoff(j) + (size_t)b * (128 * j) + 128 * MM;
                zu[e] = __ldg(g_u + base + (size_t)(tm1 >> j) * (size_t)(8192 * j) + r);
            }
        }
        // Wmm @ h^(k-1): each thread dots its 64-wide half-row against h half
        float a0 = 0.f, a1 = 0.f, a2 = 0.f, a3 = 0.f;
        const float4* h4p = (const float4*)h + half * 16;
#pragma unroll
        for (int q = 0; q < 4; q++) {
            float4 h40 = h4p[4 * q + 0], h41 = h4p[4 * q + 1];
            float4 h42 = h4p[4 * q + 2], h43 = h4p[4 * q + 3];
            float4 w0 = w[4 * q + 0], w1 = w[4 * q + 1];
            float4 w2 = w[4 * q + 2], w3 = w[4 * q + 3];
            a0 = fmaf(w0.x, h40.x, fmaf(w0.y, h40.y, fmaf(w0.z, h40.z, fmaf(w0.w, h40.w, a0))));
            a1 = fmaf(w1.x, h41.x, fmaf(w1.y, h41.y, fmaf(w1.z, h41.z, fmaf(w1.w, h41.w, a1))));
            a2 = fmaf(w2.x, h42.x, fmaf(w2.y, h42.y, fmaf(w2.z, h42.z, fmaf(w2.w, h42.w, a2))));
            a3 = fmaf(w3.x, h43.x, fmaf(w3.y, h43.y, fmaf(w3.z, h43.z, fmaf(w3.w, h43.w, a3))));
        }
        float acc = (a0 + a1) + (a2 + a3);
        if (half) ps[r] = acc;
        __syncthreads();
        if (!half) {
            float hn = tanhf(z + acc + ps[r]);
            h[r] = hn;
            ht[(size_t)k * 8192 + r] = hn;
        }
        __syncthreads();
    }
}

// ---------------------------------------------------------------------------
// Gather: y[b][t][i] = fc_b[i] + sum_m C_m[(t>>m)*64 + b][i]
// ---------------------------------------------------------------------------
__global__ __launch_bounds__(256)
void gather_y(const float* __restrict__ fcb, float* __restrict__ out)
{
    const int i = threadIdx.x;
    const float bias = __ldg(fcb + i);
#pragma unroll 1
    for (int e = 0; e < 8; e++) {
        const int tb = blockIdx.x * 8 + e;
        const int t = tb >> 6;
        const int b = tb & 63;
        float v = bias;
#pragma unroll
        for (int m = 0; m < 8; m++)
            v += g_c[coff(m) + (((size_t)((t >> m) * 64 + b)) << 8) + i];
        out[((size_t)b * 2048 + t) * 256 + i] = v;
    }
}

// ---------------------------------------------------------------------------
// Launch: 8 XP GEMMs -> cascade (chain7 .. chain0 with U/C GEMMs between)
// -> gather. 33 launches, one stream, graph-capturable, no allocations.
// ---------------------------------------------------------------------------
extern "C" void kernel_launch(void* const* d_in, const int* in_sizes, int n_in,
                              void* d_out, int out_size)
{
    const float* x   = (const float*)d_in[0];
    const float* wih = (const float*)d_in[1];
    const float* whh = (const float*)d_in[2];
    const float* bih = (const float*)d_in[3];
    const float* bhh = (const float*)d_in[4];
    const float* fcw = (const float*)d_in[5];
    const float* fcb = (const float*)d_in[6];
    float* out = (float*)d_out;

    void* p;
    cudaGetSymbolAddress(&p, g_xp); float* pxp = (float*)p;
    cudaGetSymbolAddress(&p, g_ht); float* pht = (float*)p;
    cudaGetSymbolAddress(&p, g_u);  float* pu  = (float*)p;
    cudaGetSymbolAddress(&p, g_c);  float* pc  = (float*)p;

    cudaFuncSetAttribute(gemm_tf32, cudaFuncAttributeMaxDynamicSharedMemorySize,
                         GEMM_SMEM_BYTES);

    // XP GEMMs: XP_m = x(strided t) @ Wih[m-block]^T   (K=256, N=128)
    for (int m = 0; m < 8; m++) {
        dim3 g(1, (unsigned)((2048 >> m) >> 1));   // M/128 = (2048>>m)*64/128
        gemm_tf32<<<g, 256, GEMM_SMEM_BYTES>>>(
            x, wih + (size_t)128 * m * 256, pxp + xpoff(m),
            256, 256, 128, 1, m);
    }

    // Cascade: chain j, then U_j (contributions to m<j) and C_j (fc contribution)
#define RUN_UC(j)                                                                  \
    do {                                                                           \
        dim3 gu((unsigned)(j), (unsigned)((2048 >> (j)) >> 1));                    \
        gemm_tf32<<<gu, 256, GEMM_SMEM_BYTES>>>(                                   \
            pht + xpoff(j), whh + 128 * (j), pu + uoff(j),                         \
            128, 1024, 128 * (j), 0, 0);                                           \
        dim3 gc(2, (unsigned)((2048 >> (j)) >> 1));                                \
        gemm_tf32<<<gc, 256, GEMM_SMEM_BYTES>>>(                                   \
            pht + xpoff(j), fcw + 128 * (j), pc + coff(j),                         \
            128, 1024, 256, 0, 0);                                                 \
    } while (0)

    chain_kernel<7><<<BATCH, 256>>>(whh, bih, bhh);
    RUN_UC(7);
    chain_kernel<6><<<BATCH, 256>>>(whh, bih, bhh);
    RUN_UC(6);
    chain_kernel<5><<<BATCH, 256>>>(whh, bih, bhh);
    RUN_UC(5);
    chain_kernel<4><<<BATCH, 256>>>(whh, bih, bhh);
    RUN_UC(4);
    chain_kernel<3><<<BATCH, 256>>>(whh, bih, bhh);
    RUN_UC(3);
    chain_kernel<2><<<BATCH, 256>>>(whh, bih, bhh);
    RUN_UC(2);
    chain_kernel<1><<<BATCH, 256>>>(whh, bih, bhh);
    RUN_UC(1);
    chain_kernel<0><<<BATCH, 256>>>(whh, bih, bhh);
    {   // C_0 (no U_0 needed)
        dim3 gc(2, 1024);
        gemm_tf32<<<gc, 256, GEMM_SMEM_BYTES>>>(
            pht + xpoff(0), fcw, pc + coff(0), 128, 1024, 256, 0, 0);
    }

    gather_y<<<16384, 256>>>(fcb, out);
#undef RUN_UC
}

// round 9
// speedup vs baseline: 19.2272x; 1.0858x over previous
#include <cuda_runtime.h>
#include <math.h>
#include <stdint.h>

#define BATCH 64
#define SEQT  2048
#define ISZ   256
#define HSZ   1024

// ---------------------------------------------------------------------------
// Global scratch (module-compact layouts).
//  XP_m[k][b][128] : input projection at module-m active times (t = k<<m)
//  HT_m[k][b][128] : module-m hidden trajectory samples
//  U_j [k][b][128j]: Whh[0:128j, j-block] @ h_j^(k)
//  C_m [k][b][256] : fc_w[:, m-block] @ h_m^(k)
// ---------------------------------------------------------------------------
#define XP_TOT 33423360ull
#define U_TOT  32374784ull
#define C_TOT  66846720ull
static __device__ float g_xp[XP_TOT];
static __device__ float g_ht[XP_TOT];
static __device__ float g_u [U_TOT];
static __device__ float g_c [C_TOT];

__host__ __device__ constexpr size_t xpoff(int m) {
    return 8192ull * (size_t)(4096 - (4096 >> m));
}
__host__ __device__ constexpr size_t uoff(int j) {
    size_t s = 0;
    for (int p = 1; p < j; p++) s += (size_t)(2048 >> p) * 8192ull * (size_t)p;
    return s;
}
__host__ __device__ constexpr size_t coff(int m) {
    return 16384ull * (size_t)(4096 - (4096 >> m));
}

// ---------------------------------------------------------------------------
// TF32 3-split GEMM core (fp32-accurate): 128x128 CTA tile, 256 thr, 8 warps,
// warp tile 32x64, mma.m16n8k8, double-buffered smem stage.
// ---------------------------------------------------------------------------
__device__ __forceinline__ uint32_t f32_to_tf32(float x) {
    uint32_t r;
    asm("cvt.rna.tf32.f32 %0, %1;" : "=r"(r) : "f"(x));
    return r;
}
__device__ __forceinline__ void mma_tf32(float4& d, const uint32_t a[4],
                                         const uint32_t b0, const uint32_t b1) {
    asm volatile(
        "mma.sync.aligned.m16n8k8.row.col.f32.tf32.tf32.f32 "
        "{%0,%1,%2,%3}, {%4,%5,%6,%7}, {%8,%9}, {%0,%1,%2,%3};"
        : "+f"(d.x), "+f"(d.y), "+f"(d.z), "+f"(d.w)
        : "r"(a[0]), "r"(a[1]), "r"(a[2]), "r"(a[3]), "r"(b0), "r"(b1));
}

#define GST 4224
#define GEMM_SMEM_BYTES (2 * GST * 4)

__device__ __forceinline__ void stage_chunk(float* s, const float4 av, const float4 bv,
                                            int ldr, int ldk)
{
    const float a4[4] = {av.x, av.y, av.z, av.w};
    const float b4[4] = {bv.x, bv.y, bv.z, bv.w};
#pragma unroll
    for (int e = 0; e < 4; e++) {
        uint32_t hi = f32_to_tf32(a4[e]);
        float lo = a4[e] - __uint_as_float(hi);
        s[(ldk + e) * 132 + ldr]        = __uint_as_float(hi);
        s[1056 + (ldk + e) * 132 + ldr] = __uint_as_float(f32_to_tf32(lo));
        uint32_t bhi = f32_to_tf32(b4[e]);
        float blo = b4[e] - __uint_as_float(bhi);
        s[2112 + (ldk + e) * 132 + ldr] = __uint_as_float(bhi);
        s[3168 + (ldk + e) * 132 + ldr] = __uint_as_float(f32_to_tf32(blo));
    }
}

__device__ __forceinline__ void gemm_core(const float* Ag, const float* Bg,
                                          int kchunks, float* gsm,
                                          int ldr, int ldk, int m0, int n0, int tig,
                                          float4 acc[2][8])
{
    stage_chunk(gsm, *(const float4*)Ag, *(const float4*)Bg, ldr, ldk);
    __syncthreads();

    for (int kc = 0; kc < kchunks; kc++) {
        float4 av, bv;
        if (kc + 1 < kchunks) {
            av = *(const float4*)(Ag + (kc + 1) * 8);
            bv = *(const float4*)(Bg + (kc + 1) * 8);
        }
        const float* As_h = gsm + (kc & 1) * GST;
        const float* As_l = As_h + 1056;
        const float* Bs_h = As_h + 2112;
        const float* Bs_l = As_h + 3168;

        uint32_t ah[2][4], al[2][4];
#pragma unroll
        for (int mt = 0; mt < 2; mt++) {
            const int r = m0 + mt * 16;
            ah[mt][0] = __float_as_uint(As_h[tig * 132 + r]);
            ah[mt][1] = __float_as_uint(As_h[tig * 132 + r + 8]);
            ah[mt][2] = __float_as_uint(As_h[(tig + 4) * 132 + r]);
            ah[mt][3] = __float_as_uint(As_h[(tig + 4) * 132 + r + 8]);
            al[mt][0] = __float_as_uint(As_l[tig * 132 + r]);
            al[mt][1] = __float_as_uint(As_l[tig * 132 + r + 8]);
            al[mt][2] = __float_as_uint(As_l[(tig + 4) * 132 + r]);
            al[mt][3] = __float_as_uint(As_l[(tig + 4) * 132 + r + 8]);
        }
#pragma unroll
        for (int nt = 0; nt < 8; nt++) {
            const int cn = n0 + nt * 8;
            uint32_t bh0 = __float_as_uint(Bs_h[tig * 132 + cn]);
            uint32_t bh1 = __float_as_uint(Bs_h[(tig + 4) * 132 + cn]);
            uint32_t bl0 = __float_as_uint(Bs_l[tig * 132 + cn]);
            uint32_t bl1 = __float_as_uint(Bs_l[(tig + 4) * 132 + cn]);
#pragma unroll
            for (int mt = 0; mt < 2; mt++) {
                mma_tf32(acc[mt][nt], al[mt], bh0, bh1);
                mma_tf32(acc[mt][nt], ah[mt], bl0, bl1);
                mma_tf32(acc[mt][nt], ah[mt], bh0, bh1);
            }
        }

        if (kc + 1 < kchunks)
            stage_chunk(gsm + ((kc + 1) & 1) * GST, av, bv, ldr, ldk);
        __syncthreads();
    }
}

// ---------------------------------------------------------------------------
// Fused XP GEMM: one launch for all 8 modules. blockIdx.x in [0, 2040);
// module m decoded by cumulative tile counts (1024>>m tiles each).
// XP_m = x(strided t = k<<m) @ Wih[m-block]^T, K=256, N=128.
// ---------------------------------------------------------------------------
__global__ __launch_bounds__(256, 2)
void gemm_xp(const float* __restrict__ X, const float* __restrict__ Wih)
{
    extern __shared__ float gsm[];
    const int tid = threadIdx.x;
    const int wid = tid >> 5;
    const int lane = tid & 31;
    const int grp = lane >> 2;
    const int tig = lane & 3;
    const int warpRow = wid >> 1;
    const int warpCol = wid & 1;
    const int ldr = tid >> 1;
    const int ldk = (tid & 1) << 2;

    int Y = blockIdx.x;
    int m = 0, base = 0, cnt = 1024;
    while (Y >= base + cnt && m < 7) { base += cnt; m++; cnt >>= 1; }
    const int ty = Y - base;

    const int rowg = ty * 128 + ldr;
    const int bb = rowg & 63;
    const int kk = rowg >> 6;
    const float* Ag = X + ((size_t)bb * 2048 + ((size_t)kk << m)) * 256 + ldk;
    const float* Bg = Wih + ((size_t)(128 * m + ldr)) * 256 + ldk;

    float4 acc[2][8];
#pragma unroll
    for (int i = 0; i < 2; i++)
#pragma unroll
        for (int j = 0; j < 8; j++) acc[i][j] = make_float4(0.f, 0.f, 0.f, 0.f);

    gemm_core(Ag, Bg, 32, gsm, ldr, ldk, warpRow * 32 + grp, warpCol * 64 + grp, tig, acc);

    float* C = g_xp + xpoff(m);
#pragma unroll
    for (int nt = 0; nt < 8; nt++) {
        const int col = warpCol * 64 + nt * 8 + tig * 2;
#pragma unroll
        for (int mt = 0; mt < 2; mt++) {
            const int r0 = ty * 128 + warpRow * 32 + mt * 16 + grp;
            float4 d = acc[mt][nt];
            *(float2*)(C + (size_t)r0 * 128 + col)       = make_float2(d.x, d.y);
            *(float2*)(C + (size_t)(r0 + 8) * 128 + col) = make_float2(d.z, d.w);
        }
    }
}

// ---------------------------------------------------------------------------
// Fused U+C GEMM for module j: grid.x = split + ctiles.
//   bn <  split : U part — B rows of Whh[, j-block],  out C1 (ldc1)
//   bn >= split : C part — B rows of fcw[, j-block],  out C2 (ldc2)
// A = ht_j (M = (2048>>j)*64 rows, K = 128).
// ---------------------------------------------------------------------------
__global__ __launch_bounds__(256, 2)
void gemm_uc(const float* __restrict__ A, const float* __restrict__ B1,
             const float* __restrict__ B2, float* __restrict__ C1,
             float* __restrict__ C2, int split, int ldc1)
{
    extern __shared__ float gsm[];
    const int bn = blockIdx.x;
    const int bm = blockIdx.y;
    const int tid = threadIdx.x;
    const int wid = tid >> 5;
    const int lane = tid & 31;
    const int grp = lane >> 2;
    const int tig = lane & 3;
    const int warpRow = wid >> 1;
    const int warpCol = wid & 1;
    const int ldr = tid >> 1;
    const int ldk = (tid & 1) << 2;

    const int isU = (bn < split);
    const int bnl = isU ? bn : bn - split;
    const float* Bbase = isU ? B1 : B2;

    const float* Ag = A + (size_t)(bm * 128 + ldr) * 128 + ldk;
    const float* Bg = Bbase + (size_t)(bnl * 128 + ldr) * 1024 + ldk;

    float4 acc[2][8];
#pragma unroll
    for (int i = 0; i < 2; i++)
#pragma unroll
        for (int j = 0; j < 8; j++) acc[i][j] = make_float4(0.f, 0.f, 0.f, 0.f);

    gemm_core(Ag, Bg, 16, gsm, ldr, ldk, warpRow * 32 + grp, warpCol * 64 + grp, tig, acc);

    float* C = isU ? C1 : C2;
    const int ldc = isU ? ldc1 : 256;
#pragma unroll
    for (int nt = 0; nt < 8; nt++) {
        const int col = bnl * 128 + warpCol * 64 + nt * 8 + tig * 2;
#pragma unroll
        for (int mt = 0; mt < 2; mt++) {
            const int r0 = bm * 128 + warpRow * 32 + mt * 16 + grp;
            float4 d = acc[mt][nt];
            *(float2*)(C + (size_t)r0 * ldc + col)       = make_float2(d.x, d.y);
            *(float2*)(C + (size_t)(r0 + 8) * ldc + col) = make_float2(d.z, d.w);
        }
    }
}

// ---------------------------------------------------------------------------
// Chain kernel (template on module MM): sequential 128-dim recurrence.
// ---------------------------------------------------------------------------
template<int MM>
__global__ __launch_bounds__(256, 1)
void chain_kernel(const float* __restrict__ Whh, const float* __restrict__ bih,
                  const float* __restrict__ bhh)
{
    const int b = blockIdx.x;
    const int tid = threadIdx.x;
    const int r = tid & 127;
    const int half = tid >> 7;

    float4 w[16];
    const float4* wrow = (const float4*)(Whh + (size_t)(128 * MM + r) * 1024 + 128 * MM + 64 * half);
#pragma unroll
    for (int q = 0; q < 16; q++) w[q] = __ldg(wrow + q);

    float bsr = 0.f;
    if (half == 0) bsr = __ldg(bih + 128 * MM + r) + __ldg(bhh + 128 * MM + r);

    __shared__ __align__(16) float h[128];
    __shared__ float ps[128];
    if (tid < 128) h[tid] = 0.f;
    __syncthreads();

    constexpr int KS = 2048 >> MM;
    constexpr int NU = 7 - MM;
    const float* xp = g_xp + xpoff(MM) + (size_t)b * 128;
    float* ht = g_ht + xpoff(MM) + (size_t)b * 128;

    float zx = 0.f;
    float zu[NU > 0 ? NU : 1];
#pragma unroll
    for (int e = 0; e < NU; e++) zu[e] = 0.f;
    if (half == 0) zx = __ldg(xp + r);

    for (int k = 0; k < KS; k++) {
        float z = 0.f;
        if (half == 0) {
            z = zx + bsr;
            if (k > 0) {
#pragma unroll
                for (int e = 0; e < NU; e++) z += zu[e];
            }
        }
        if (half == 0 && k + 1 < KS) {
            zx = __ldg(xp + (size_t)(k + 1) * 8192 + r);
            const int tm1 = ((k + 1) << MM) - 1;
#pragma unroll
            for (int e = 0; e < NU; e++) {
                const int j = MM + 1 + e;
                const size_t base = uoff(j) + (size_t)b * (128 * j) + 128 * MM;
                zu[e] = __ldg(g_u + base + (size_t)(tm1 >> j) * (size_t)(8192 * j) + r);
            }
        }
        float a0 = 0.f, a1 = 0.f, a2 = 0.f, a3 = 0.f;
        const float4* h4p = (const float4*)h + half * 16;
#pragma unroll
        for (int q = 0; q < 4; q++) {
            float4 h40 = h4p[4 * q + 0], h41 = h4p[4 * q + 1];
            float4 h42 = h4p[4 * q + 2], h43 = h4p[4 * q + 3];
            float4 w0 = w[4 * q + 0], w1 = w[4 * q + 1];
            float4 w2 = w[4 * q + 2], w3 = w[4 * q + 3];
            a0 = fmaf(w0.x, h40.x, fmaf(w0.y, h40.y, fmaf(w0.z, h40.z, fmaf(w0.w, h40.w, a0))));
            a1 = fmaf(w1.x, h41.x, fmaf(w1.y, h41.y, fmaf(w1.z, h41.z, fmaf(w1.w, h41.w, a1))));
            a2 = fmaf(w2.x, h42.x, fmaf(w2.y, h42.y, fmaf(w2.z, h42.z, fmaf(w2.w, h42.w, a2))));
            a3 = fmaf(w3.x, h43.x, fmaf(w3.y, h43.y, fmaf(w3.z, h43.z, fmaf(w3.w, h43.w, a3))));
        }
        float acc = (a0 + a1) + (a2 + a3);
        if (half) ps[r] = acc;
        __syncthreads();
        if (!half) {
            float hn = tanhf(z + acc + ps[r]);
            h[r] = hn;
            ht[(size_t)k * 8192 + r] = hn;
        }
        __syncthreads();
    }
}

// ---------------------------------------------------------------------------
// Gather: y[b][t][i] = fc_b[i] + sum_m C_m[(t>>m)*64 + b][i]
// ---------------------------------------------------------------------------
__global__ __launch_bounds__(256)
void gather_y(const float* __restrict__ fcb, float* __restrict__ out)
{
    const int i = threadIdx.x;
    const float bias = __ldg(fcb + i);
#pragma unroll 1
    for (int e = 0; e < 8; e++) {
        const int tb = blockIdx.x * 8 + e;
        const int t = tb >> 6;
        const int b = tb & 63;
        float v = bias;
#pragma unroll
        for (int m = 0; m < 8; m++)
            v += g_c[coff(m) + (((size_t)((t >> m) * 64 + b)) << 8) + i];
        out[((size_t)b * 2048 + t) * 256 + i] = v;
    }
}

// ---------------------------------------------------------------------------
// Launch: XP(1) -> [chain_j -> UC_j]_{j=7..1} -> chain_0 -> C0 -> gather.
// 18 launches, one stream, graph-capturable, allocation-free.
// ---------------------------------------------------------------------------
extern "C" void kernel_launch(void* const* d_in, const int* in_sizes, int n_in,
                              void* d_out, int out_size)
{
    const float* x   = (const float*)d_in[0];
    const float* wih = (const float*)d_in[1];
    const float* whh = (const float*)d_in[2];
    const float* bih = (const float*)d_in[3];
    const float* bhh = (const float*)d_in[4];
    const float* fcw = (const float*)d_in[5];
    const float* fcb = (const float*)d_in[6];
    float* out = (float*)d_out;

    void* p;
    cudaGetSymbolAddress(&p, g_ht); float* pht = (float*)p;
    cudaGetSymbolAddress(&p, g_u);  float* pu  = (float*)p;
    cudaGetSymbolAddress(&p, g_c);  float* pc  = (float*)p;

    cudaFuncSetAttribute(gemm_xp, cudaFuncAttributeMaxDynamicSharedMemorySize,
                         GEMM_SMEM_BYTES);
    cudaFuncSetAttribute(gemm_uc, cudaFuncAttributeMaxDynamicSharedMemorySize,
                         GEMM_SMEM_BYTES);

    // all input projections in one full-chip launch (2040 tiles)
    gemm_xp<<<2040, 256, GEMM_SMEM_BYTES>>>(x, wih);

    // cascade: chain_j, then fused U_j (split=j) + C_j (2 tiles) GEMM
#define RUN_STAGE(j)                                                            \
    do {                                                                        \
        chain_kernel<j><<<BATCH, 256>>>(whh, bih, bhh);                         \
        dim3 g((unsigned)((j) + 2), (unsigned)(1024 >> (j)));                   \
        gemm_uc<<<g, 256, GEMM_SMEM_BYTES>>>(                                   \
            pht + xpoff(j), whh + 128 * (j), fcw + 128 * (j),                   \
            pu + uoff(j), pc + coff(j), (j), 128 * (j));                        \
    } while (0)

    RUN_STAGE(7);
    RUN_STAGE(6);
    RUN_STAGE(5);
    RUN_STAGE(4);
    RUN_STAGE(3);
    RUN_STAGE(2);
    RUN_STAGE(1);

    chain_kernel<0><<<BATCH, 256>>>(whh, bih, bhh);
    {   // C_0: split=0 -> both column tiles route to the fc output
        dim3 g(2, 1024);
        gemm_uc<<<g, 256, GEMM_SMEM_BYTES>>>(
            pht + xpoff(0), fcw, fcw, pc + coff(0), pc + coff(0), 0, 256);
    }

    gather_y<<<16384, 256>>>(fcb, out);
#undef RUN_STAGE
}